// round 3
// baseline (speedup 1.0000x reference)
#include <cuda_runtime.h>
#include <math.h>

#define Bq 4
#define Nq 8192
#define Dq 1024
#define Hq 8
#define HDq 128
#define TDq 3072
#define KV_SPLIT 16

__device__ float g_xn[(size_t)Bq * Nq * Dq];        // 128 MB normalized x
__device__ float g_qkv[(size_t)Bq * Nq * TDq];      // 384 MB activated q|k|v
__device__ float g_kv[(size_t)Bq * Hq * HDq * HDq]; // 2 MB per-head kv
__device__ float g_maskf[(size_t)Bq * Nq];          // canonical k-mask multiplier
__device__ int   g_mask_is_i32;                     // dtype detector flag

// ---------------------------------------------------------------------------
// Kernel 0a: detect mask encoding. int32 bools -> every word in {0,1}.
// uint8-packed bools read as int32 -> words like 0x01010101 (not 0/1).
// Deterministic: same input bytes -> same flag on every call.
// ---------------------------------------------------------------------------
__global__ void mask_detect(const int* __restrict__ m) {
    __shared__ int bad[8];
    int mybad = 0;
    for (int i = threadIdx.x; i < 4096; i += blockDim.x) {
        const int v = m[i];
        if (v != 0 && v != 1) mybad = 1;
    }
    #pragma unroll
    for (int o = 16; o > 0; o >>= 1) mybad |= __shfl_down_sync(0xffffffffu, mybad, o);
    if ((threadIdx.x & 31) == 0) bad[threadIdx.x >> 5] = mybad;
    __syncthreads();
    if (threadIdx.x == 0) {
        int t = 0;
        #pragma unroll
        for (int i = 0; i < 8; i++) t |= bad[i];
        g_mask_is_i32 = t ? 0 : 1;
    }
}

// ---------------------------------------------------------------------------
// Kernel 0b: canonicalize mask to float multiplier (mask true -> 0.0).
// ---------------------------------------------------------------------------
__global__ void mask_expand(const void* __restrict__ m) {
    const int i = blockIdx.x * blockDim.x + threadIdx.x;
    if (i >= Bq * Nq) return;
    int set;
    if (g_mask_is_i32) set = ((const int*)m)[i] != 0;
    else               set = ((const unsigned char*)m)[i] != 0;
    g_maskf[i] = set ? 0.0f : 1.0f;
}

// ---------------------------------------------------------------------------
// Kernel 1: LayerNorm. One block per row (B*N rows), 256 threads, 4 floats each.
// ---------------------------------------------------------------------------
__global__ void ln_kernel(const float* __restrict__ x,
                          const float* __restrict__ gamma,
                          const float* __restrict__ beta) {
    const int row = blockIdx.x;
    const int t = threadIdx.x;
    const float4 a = reinterpret_cast<const float4*>(x + (size_t)row * Dq)[t];
    float s  = a.x + a.y + a.z + a.w;
    float ss = a.x * a.x + a.y * a.y + a.z * a.z + a.w * a.w;

    __shared__ float red[16];
    __shared__ float mv[2];
    #pragma unroll
    for (int o = 16; o > 0; o >>= 1) {
        s  += __shfl_down_sync(0xffffffffu, s, o);
        ss += __shfl_down_sync(0xffffffffu, ss, o);
    }
    const int w = t >> 5, l = t & 31;
    if (l == 0) { red[w] = s; red[w + 8] = ss; }
    __syncthreads();
    if (t == 0) {
        float ts = 0.f, tss = 0.f;
        #pragma unroll
        for (int i = 0; i < 8; i++) { ts += red[i]; tss += red[i + 8]; }
        const float mean = ts * (1.0f / Dq);
        const float var  = tss * (1.0f / Dq) - mean * mean;
        mv[0] = mean;
        mv[1] = rsqrtf(var + 1e-5f);
    }
    __syncthreads();
    const float mean = mv[0], rstd = mv[1];
    const float4 g4 = reinterpret_cast<const float4*>(gamma)[t];
    const float4 b4 = reinterpret_cast<const float4*>(beta)[t];
    float4 o;
    o.x = (a.x - mean) * rstd * g4.x + b4.x;
    o.y = (a.y - mean) * rstd * g4.y + b4.y;
    o.z = (a.z - mean) * rstd * g4.z + b4.z;
    o.w = (a.w - mean) * rstd * g4.w + b4.w;
    reinterpret_cast<float4*>(g_xn + (size_t)row * Dq)[t] = o;
}

// ---------------------------------------------------------------------------
// Kernel 2: QKV GEMM [32768 x 3072 x 1024] fp32, 128x128 tile, BK=8,
// 256 threads, 8x8 per thread. Fused epilogue: sigmoid / tanh+mask / identity.
// Column-block -> section mapping is uniform per block (each section = 8 blocks).
// ---------------------------------------------------------------------------
__global__ __launch_bounds__(256, 2)
void qkv_gemm(const float* __restrict__ W) {
    __shared__ float As[8][128];
    __shared__ float Bs[8][128];
    const int tid = threadIdx.x;
    const int tx = tid & 15, ty = tid >> 4;
    const int row0 = blockIdx.y * 128;
    const int col0 = blockIdx.x * 128;

    const int ar = tid >> 1;          // A tile: row within 128
    const int ac = (tid & 1) * 4;     // A tile: k within 8
    const int br = tid >> 5;          // B tile: k within 8
    const int bc = (tid & 31) * 4;    // B tile: col within 128

    const float* Aptr = g_xn + (size_t)(row0 + ar) * Dq + ac;
    const float* Bptr = W + (size_t)br * TDq + col0 + bc;

    float acc[8][8];
    #pragma unroll
    for (int i = 0; i < 8; i++)
        #pragma unroll
        for (int j = 0; j < 8; j++) acc[i][j] = 0.f;

    for (int k0 = 0; k0 < Dq; k0 += 8) {
        const float4 av = *reinterpret_cast<const float4*>(Aptr + k0);
        const float4 bv = *reinterpret_cast<const float4*>(Bptr + (size_t)k0 * TDq);
        As[ac + 0][ar] = av.x; As[ac + 1][ar] = av.y;
        As[ac + 2][ar] = av.z; As[ac + 3][ar] = av.w;
        *reinterpret_cast<float4*>(&Bs[br][bc]) = bv;
        __syncthreads();
        #pragma unroll
        for (int kk = 0; kk < 8; kk++) {
            float a[8], b[8];
            #pragma unroll
            for (int i = 0; i < 8; i++) a[i] = As[kk][ty * 8 + i];
            #pragma unroll
            for (int j = 0; j < 8; j++) b[j] = Bs[kk][tx * 8 + j];
            #pragma unroll
            for (int i = 0; i < 8; i++)
                #pragma unroll
                for (int j = 0; j < 8; j++) acc[i][j] += a[i] * b[j];
        }
        __syncthreads();
    }

    const int sec = blockIdx.x >> 3;   // 0=q, 1=k, 2=v (block-uniform)
    #pragma unroll
    for (int i = 0; i < 8; i++) {
        const int r = row0 + ty * 8 + i;
        const float mfac = (sec == 1) ? g_maskf[r] : 1.0f;
        float* op = g_qkv + (size_t)r * TDq + col0 + tx * 8;
        #pragma unroll
        for (int j = 0; j < 8; j++) {
            float v = acc[i][j];
            if (sec == 0)      v = 1.0f / (1.0f + expf(-v));
            else if (sec == 1) v = tanhf(v) * mfac;
            op[j] = v;
        }
    }
}

// ---------------------------------------------------------------------------
// Kernel 3a: zero the kv accumulator (must run every launch: graph replays).
// ---------------------------------------------------------------------------
__global__ void zero_kv() {
    const int i = blockIdx.x * blockDim.x + threadIdx.x;
    if (i < Bq * Hq * HDq * HDq) g_kv[i] = 0.f;
}

// ---------------------------------------------------------------------------
// Kernel 3b: kv[b,h] = sum_n k[b,h,n,:]^T v[b,h,n,:]. Split-K over N with
// fp32 atomicAdd so 512 blocks cover the chip instead of 32.
// ---------------------------------------------------------------------------
__global__ __launch_bounds__(256, 2)
void kv_gemm() {
    __shared__ float ks[8][128];
    __shared__ float vs[8][128];
    const int bh = blockIdx.x;            // 0..31
    const int split = blockIdx.y;         // 0..KV_SPLIT-1
    const int b = bh >> 3, h = bh & 7;
    const int tid = threadIdx.x;
    const int tx = tid & 15, ty = tid >> 4;
    const int lr = tid >> 5;              // 0..7 (n within stage)
    const int lc = (tid & 31) * 4;        // 0..124 (head dim)

    const int nchunk = Nq / KV_SPLIT;     // 512
    const int n0 = split * nchunk;
    const float* kbase = g_qkv + (size_t)(b * Nq + n0 + lr) * TDq + Dq + h * HDq + lc;
    const float* vbase = kbase + Dq;      // v section

    float acc[8][8];
    #pragma unroll
    for (int i = 0; i < 8; i++)
        #pragma unroll
        for (int j = 0; j < 8; j++) acc[i][j] = 0.f;

    for (int nn = 0; nn < nchunk; nn += 8) {
        const float4 kv4 = *reinterpret_cast<const float4*>(kbase + (size_t)nn * TDq);
        const float4 vv4 = *reinterpret_cast<const float4*>(vbase + (size_t)nn * TDq);
        *reinterpret_cast<float4*>(&ks[lr][lc]) = kv4;
        *reinterpret_cast<float4*>(&vs[lr][lc]) = vv4;
        __syncthreads();
        #pragma unroll
        for (int kk = 0; kk < 8; kk++) {
            float a[8], c[8];
            #pragma unroll
            for (int i = 0; i < 8; i++) a[i] = ks[kk][ty * 8 + i];
            #pragma unroll
            for (int j = 0; j < 8; j++) c[j] = vs[kk][tx * 8 + j];
            #pragma unroll
            for (int i = 0; i < 8; i++)
                #pragma unroll
                for (int j = 0; j < 8; j++) acc[i][j] += a[i] * c[j];
        }
        __syncthreads();
    }

    float* out = g_kv + (size_t)bh * HDq * HDq;
    #pragma unroll
    for (int i = 0; i < 8; i++)
        #pragma unroll
        for (int j = 0; j < 8; j++)
            atomicAdd(&out[(ty * 8 + i) * HDq + tx * 8 + j], acc[i][j]);
}

// ---------------------------------------------------------------------------
// Kernel 4: out[b,h] = q[b,h] @ kv[b,h].  q: [8192,128] (stride TDq), kv 128x128.
// ---------------------------------------------------------------------------
__global__ __launch_bounds__(256, 2)
void out_gemm(float* __restrict__ out) {
    __shared__ float qs[8][128];
    __shared__ float cs[8][128];
    const int bh = blockIdx.y;            // 0..31
    const int b = bh >> 3, h = bh & 7;
    const int n0 = blockIdx.x * 128;
    const int tid = threadIdx.x;
    const int tx = tid & 15, ty = tid >> 4;
    const int ar = tid >> 1, ac = (tid & 1) * 4;
    const int br = tid >> 5, bc = (tid & 31) * 4;

    const float* qptr  = g_qkv + (size_t)(b * Nq + n0 + ar) * TDq + h * HDq + ac;
    const float* kvptr = g_kv + ((size_t)bh * HDq + br) * HDq + bc;

    float acc[8][8];
    #pragma unroll
    for (int i = 0; i < 8; i++)
        #pragma unroll
        for (int j = 0; j < 8; j++) acc[i][j] = 0.f;

    for (int k0 = 0; k0 < HDq; k0 += 8) {
        const float4 qv = *reinterpret_cast<const float4*>(qptr + k0);
        const float4 cv = *reinterpret_cast<const float4*>(kvptr + (size_t)k0 * HDq);
        qs[ac + 0][ar] = qv.x; qs[ac + 1][ar] = qv.y;
        qs[ac + 2][ar] = qv.z; qs[ac + 3][ar] = qv.w;
        *reinterpret_cast<float4*>(&cs[br][bc]) = cv;
        __syncthreads();
        #pragma unroll
        for (int kk = 0; kk < 8; kk++) {
            float a[8], c[8];
            #pragma unroll
            for (int i = 0; i < 8; i++) a[i] = qs[kk][ty * 8 + i];
            #pragma unroll
            for (int j = 0; j < 8; j++) c[j] = cs[kk][tx * 8 + j];
            #pragma unroll
            for (int i = 0; i < 8; i++)
                #pragma unroll
                for (int j = 0; j < 8; j++) acc[i][j] += a[i] * c[j];
        }
        __syncthreads();
    }

    #pragma unroll
    for (int i = 0; i < 8; i++) {
        const int n = n0 + ty * 8 + i;
        float* op = out + (size_t)(b * Nq + n) * Dq + h * HDq + tx * 8;
        #pragma unroll
        for (int j = 0; j < 8; j++) op[j] = acc[i][j];
    }
}

// ---------------------------------------------------------------------------
// Launch: inputs in metadata order: x, mask, w_qkv, gamma, beta.
// ---------------------------------------------------------------------------
extern "C" void kernel_launch(void* const* d_in, const int* in_sizes, int n_in,
                              void* d_out, int out_size) {
    const float* x     = (const float*)d_in[0];
    const void*  mask  = d_in[1];
    const float* w     = (const float*)d_in[2];
    const float* gamma = (const float*)d_in[3];
    const float* beta  = (const float*)d_in[4];
    float* out         = (float*)d_out;

    mask_detect<<<1, 256>>>((const int*)mask);
    mask_expand<<<(Bq * Nq + 255) / 256, 256>>>(mask);
    ln_kernel<<<Bq * Nq, 256>>>(x, gamma, beta);
    qkv_gemm<<<dim3(TDq / 128, (Bq * Nq) / 128), 256>>>(w);
    zero_kv<<<(Bq * Hq * HDq * HDq + 255) / 256, 256>>>();
    kv_gemm<<<dim3(Bq * Hq, KV_SPLIT), 256>>>();
    out_gemm<<<dim3(Nq / 128, Bq * Hq), 256>>>(out);
}

// round 5
// speedup vs baseline: 1.6061x; 1.6061x over previous
#include <cuda_runtime.h>
#include <cuda_bf16.h>
#include <math.h>
#include <stdint.h>

#define Bq 4
#define Nq 8192
#define Dq 1024
#define Hq 8
#define HDq 128
#define TDq 3072
#define KV_SPLIT 16

// ---------------------------------------------------------------------------
// Device scratch (no allocation allowed in kernel_launch).
// ---------------------------------------------------------------------------
__device__ __align__(16) __nv_bfloat16 g_xh[(size_t)Bq * Nq * Dq];   // LN(x) hi
__device__ __align__(16) __nv_bfloat16 g_xl[(size_t)Bq * Nq * Dq];   // LN(x) lo
__device__ __align__(16) __nv_bfloat16 g_wth[(size_t)TDq * Dq];      // W^T hi [3072,1024]
__device__ __align__(16) __nv_bfloat16 g_wtl[(size_t)TDq * Dq];      // W^T lo
__device__ __align__(16) float g_qkv[(size_t)Bq * Nq * TDq];         // activated q|k|v
__device__ __align__(16) float g_kv[(size_t)Bq * Hq * HDq * HDq];    // per-head kv
__device__ float g_maskf[(size_t)Bq * Nq];
__device__ int   g_mask_is_i32;

// ---------------------------------------------------------------------------
// PTX helpers (sm_80-level only: mma.sync / ldmatrix / cp.async — these
// compile for base compute_103; tcgen05 does NOT, per R4 ptxas evidence).
// ---------------------------------------------------------------------------
__device__ __forceinline__ uint32_t smem_u32(const void* p) {
    uint32_t a;
    asm("{ .reg .u64 t; cvta.to.shared.u64 t, %1; cvt.u32.u64 %0, t; }" : "=r"(a) : "l"(p));
    return a;
}
#define CP_ASYNC16(saddr, gptr) \
    asm volatile("cp.async.cg.shared.global [%0], [%1], 16;" :: "r"(saddr), "l"(gptr))
#define CP_COMMIT() asm volatile("cp.async.commit_group;" ::: "memory")
#define CP_WAIT(n)  asm volatile("cp.async.wait_group %0;" :: "n"(n) : "memory")

#define LDSM4(R0, R1, R2, R3, addr) \
    asm volatile("ldmatrix.sync.aligned.m8n8.x4.shared.b16 {%0,%1,%2,%3}, [%4];" \
                 : "=r"(R0), "=r"(R1), "=r"(R2), "=r"(R3) : "r"(addr))

#define MMA16816(d, a0, a1, a2, a3, b0, b1) \
    asm volatile("mma.sync.aligned.m16n8k16.row.col.f32.bf16.bf16.f32 " \
                 "{%0,%1,%2,%3}, {%4,%5,%6,%7}, {%8,%9}, {%0,%1,%2,%3};" \
                 : "+f"((d)[0]), "+f"((d)[1]), "+f"((d)[2]), "+f"((d)[3]) \
                 : "r"(a0), "r"(a1), "r"(a2), "r"(a3), "r"(b0), "r"(b1))

// ---------------------------------------------------------------------------
// Kernel 0a/0b: mask dtype detect + canonicalize.
// ---------------------------------------------------------------------------
__global__ void mask_detect(const int* __restrict__ m) {
    __shared__ int bad[8];
    int mybad = 0;
    for (int i = threadIdx.x; i < 4096; i += blockDim.x) {
        const int v = m[i];
        if (v != 0 && v != 1) mybad = 1;
    }
    #pragma unroll
    for (int o = 16; o > 0; o >>= 1) mybad |= __shfl_down_sync(0xffffffffu, mybad, o);
    if ((threadIdx.x & 31) == 0) bad[threadIdx.x >> 5] = mybad;
    __syncthreads();
    if (threadIdx.x == 0) {
        int t = 0;
        #pragma unroll
        for (int i = 0; i < 8; i++) t |= bad[i];
        g_mask_is_i32 = t ? 0 : 1;
    }
}
__global__ void mask_expand(const void* __restrict__ m) {
    const int i = blockIdx.x * blockDim.x + threadIdx.x;
    if (i >= Bq * Nq) return;
    int set;
    if (g_mask_is_i32) set = ((const int*)m)[i] != 0;
    else               set = ((const unsigned char*)m)[i] != 0;
    g_maskf[i] = set ? 0.0f : 1.0f;
}

// ---------------------------------------------------------------------------
// Kernel 1: LayerNorm + bf16 hi/lo split.
// ---------------------------------------------------------------------------
__device__ __forceinline__ void bsplit(float v, __nv_bfloat16& h, __nv_bfloat16& l) {
    h = __float2bfloat16(v);
    l = __float2bfloat16(v - __bfloat162float(h));
}
__global__ void ln_split(const float* __restrict__ x,
                         const float* __restrict__ gamma,
                         const float* __restrict__ beta) {
    const int row = blockIdx.x;
    const int t = threadIdx.x;
    const float4 a = reinterpret_cast<const float4*>(x + (size_t)row * Dq)[t];
    float s  = a.x + a.y + a.z + a.w;
    float ss = a.x * a.x + a.y * a.y + a.z * a.z + a.w * a.w;

    __shared__ float red[16];
    __shared__ float mv[2];
    #pragma unroll
    for (int o = 16; o > 0; o >>= 1) {
        s  += __shfl_down_sync(0xffffffffu, s, o);
        ss += __shfl_down_sync(0xffffffffu, ss, o);
    }
    const int w = t >> 5, l = t & 31;
    if (l == 0) { red[w] = s; red[w + 8] = ss; }
    __syncthreads();
    if (t == 0) {
        float ts = 0.f, tss = 0.f;
        #pragma unroll
        for (int i = 0; i < 8; i++) { ts += red[i]; tss += red[i + 8]; }
        const float mean = ts * (1.0f / Dq);
        const float var  = tss * (1.0f / Dq) - mean * mean;
        mv[0] = mean;
        mv[1] = rsqrtf(var + 1e-5f);
    }
    __syncthreads();
    const float mean = mv[0], rstd = mv[1];
    const float4 g4 = reinterpret_cast<const float4*>(gamma)[t];
    const float4 b4 = reinterpret_cast<const float4*>(beta)[t];
    float o0 = (a.x - mean) * rstd * g4.x + b4.x;
    float o1 = (a.y - mean) * rstd * g4.y + b4.y;
    float o2 = (a.z - mean) * rstd * g4.z + b4.z;
    float o3 = (a.w - mean) * rstd * g4.w + b4.w;
    __nv_bfloat16 h0, h1, h2, h3, l0, l1, l2, l3;
    bsplit(o0, h0, l0); bsplit(o1, h1, l1); bsplit(o2, h2, l2); bsplit(o3, h3, l3);
    const size_t idx = (size_t)row * Dq + t * 4;
    *reinterpret_cast<__nv_bfloat162*>(g_xh + idx)     = __nv_bfloat162(h0, h1);
    *reinterpret_cast<__nv_bfloat162*>(g_xh + idx + 2) = __nv_bfloat162(h2, h3);
    *reinterpret_cast<__nv_bfloat162*>(g_xl + idx)     = __nv_bfloat162(l0, l1);
    *reinterpret_cast<__nv_bfloat162*>(g_xl + idx + 2) = __nv_bfloat162(l2, l3);
}

// ---------------------------------------------------------------------------
// Kernel 2: W [1024,3072] fp32 -> W^T [3072,1024] bf16 hi/lo.
// ---------------------------------------------------------------------------
__global__ void w_split(const float* __restrict__ W) {
    __shared__ float tile[32][33];
    const int n0 = blockIdx.x * 32;
    const int k0 = blockIdx.y * 32;
    const int tx = threadIdx.x, ty = threadIdx.y;
    #pragma unroll
    for (int j = 0; j < 4; j++)
        tile[ty + 8 * j][tx] = W[(size_t)(k0 + ty + 8 * j) * TDq + n0 + tx];
    __syncthreads();
    #pragma unroll
    for (int j = 0; j < 4; j++) {
        const float v = tile[tx][ty + 8 * j];
        __nv_bfloat16 h, l;
        bsplit(v, h, l);
        const size_t o = (size_t)(n0 + ty + 8 * j) * Dq + k0 + tx;
        g_wth[o] = h;
        g_wtl[o] = l;
    }
}

// ---------------------------------------------------------------------------
// Kernel 3: HMMA (mma.sync) QKV GEMM, bf16x3 split, fused activation epilogue.
// 128x128 tile, BK=64 bf16 (128B rows, u^(r&7) swizzle), 3-stage cp.async,
// 8 warps (4m x 2n), 256 threads, 1 CTA/SM (192KB smem).
// ---------------------------------------------------------------------------
#define TILE_B   16384          // one 128x64 bf16 tile = 128 rows * 128B
#define STAGE_B  (4 * TILE_B)   // Ah, Al, Bh, Bl
#define NSTAGE   3
#define QKV_SMEM (NSTAGE * STAGE_B)

__device__ __forceinline__ uint32_t swz(int r, int u) {  // byte offset in tile
    return (uint32_t)(r * 128 + ((u ^ (r & 7)) << 4));
}

__global__ __launch_bounds__(256, 1) void mma_qkv_gemm() {
    extern __shared__ char smem[];
    const uint32_t su = smem_u32(smem);
    const int tid = threadIdx.x;
    const int lane = tid & 31;
    const int wid = tid >> 5;
    const int warp_m = wid & 3;          // 0..3 -> 32 rows each
    const int warp_n = wid >> 2;         // 0..1 -> 64 cols each
    const int row0 = blockIdx.y * 128;
    const int col0 = blockIdx.x * 128;

    const char* gsrc0 = (const char*)g_xh  + (size_t)row0 * 2048;
    const char* gsrc1 = (const char*)g_xl  + (size_t)row0 * 2048;
    const char* gsrc2 = (const char*)g_wth + (size_t)col0 * 2048;
    const char* gsrc3 = (const char*)g_wtl + (size_t)col0 * 2048;

    // -------- async load of one k-chunk (64 bf16) into stage s ------------
    auto load_stage = [&](int s, int c) {
        const uint32_t sb = su + s * STAGE_B;
        const size_t kb = (size_t)c * 128;       // byte offset along K
        #pragma unroll
        for (int i = 0; i < 4; ++i) {
            const int w = tid + i * 256;         // 0..1023 (16B units of one tile)
            const int r = w >> 3;
            const int u = w & 7;
            const uint32_t so = swz(r, u);
            const size_t go = (size_t)r * 2048 + kb + (size_t)u * 16;
            CP_ASYNC16(sb + 0 * TILE_B + so, gsrc0 + go);
            CP_ASYNC16(sb + 1 * TILE_B + so, gsrc1 + go);
            CP_ASYNC16(sb + 2 * TILE_B + so, gsrc2 + go);
            CP_ASYNC16(sb + 3 * TILE_B + so, gsrc3 + go);
        }
    };

    float acc[2][8][4];
    #pragma unroll
    for (int mt = 0; mt < 2; mt++)
        #pragma unroll
        for (int nt = 0; nt < 8; nt++)
            #pragma unroll
            for (int k = 0; k < 4; k++) acc[mt][nt][k] = 0.f;

    load_stage(0, 0); CP_COMMIT();
    load_stage(1, 1); CP_COMMIT();

    for (int c = 0; c < 16; ++c) {
        if (c + 2 < 16) {
            load_stage((c + 2) % NSTAGE, c + 2); CP_COMMIT();
            CP_WAIT(2);
        } else if (c + 1 < 16) {
            CP_WAIT(1);
        } else {
            CP_WAIT(0);
        }
        __syncthreads();

        const uint32_t sb = su + (c % NSTAGE) * STAGE_B;
        #pragma unroll
        for (int kk = 0; kk < 4; ++kk) {
            // A fragments (hi/lo), 2 m-tiles each
            uint32_t ah[2][4], al[2][4];
            #pragma unroll
            for (int mt = 0; mt < 2; ++mt) {
                const int r = warp_m * 32 + mt * 16 + (lane & 15);
                const int u = kk * 2 + (lane >> 4);
                const uint32_t so = swz(r, u);
                LDSM4(ah[mt][0], ah[mt][1], ah[mt][2], ah[mt][3], sb + 0 * TILE_B + so);
                LDSM4(al[mt][0], al[mt][1], al[mt][2], al[mt][3], sb + 1 * TILE_B + so);
            }
            // B fragments (hi/lo), 8 n-tiles as 4 x4-loads each
            uint32_t bh[4][4], bl[4][4];
            #pragma unroll
            for (int p = 0; p < 4; ++p) {
                const int rn = warp_n * 64 + p * 16 + (lane & 7) + ((lane >> 4) & 1) * 8;
                const int u = kk * 2 + ((lane >> 3) & 1);
                const uint32_t so = swz(rn, u);
                LDSM4(bh[p][0], bh[p][1], bh[p][2], bh[p][3], sb + 2 * TILE_B + so);
                LDSM4(bl[p][0], bl[p][1], bl[p][2], bl[p][3], sb + 3 * TILE_B + so);
            }
            #pragma unroll
            for (int mt = 0; mt < 2; ++mt)
                #pragma unroll
                for (int p = 0; p < 4; ++p) {
                    MMA16816(acc[mt][2 * p],     ah[mt][0], ah[mt][1], ah[mt][2], ah[mt][3], bh[p][0], bh[p][1]);
                    MMA16816(acc[mt][2 * p + 1], ah[mt][0], ah[mt][1], ah[mt][2], ah[mt][3], bh[p][2], bh[p][3]);
                    MMA16816(acc[mt][2 * p],     ah[mt][0], ah[mt][1], ah[mt][2], ah[mt][3], bl[p][0], bl[p][1]);
                    MMA16816(acc[mt][2 * p + 1], ah[mt][0], ah[mt][1], ah[mt][2], ah[mt][3], bl[p][2], bl[p][3]);
                    MMA16816(acc[mt][2 * p],     al[mt][0], al[mt][1], al[mt][2], al[mt][3], bh[p][0], bh[p][1]);
                    MMA16816(acc[mt][2 * p + 1], al[mt][0], al[mt][1], al[mt][2], al[mt][3], bh[p][2], bh[p][3]);
                }
        }
        __syncthreads();
    }

    // -------- epilogue: activation + store --------------------------------
    const int sec = blockIdx.x >> 3;     // 0=q, 1=k, 2=v (block-uniform)
    #pragma unroll
    for (int mt = 0; mt < 2; ++mt) {
        const int r0 = row0 + warp_m * 32 + mt * 16 + (lane >> 2);
        const int r1 = r0 + 8;
        const float m0 = (sec == 1) ? g_maskf[r0] : 1.0f;
        const float m1 = (sec == 1) ? g_maskf[r1] : 1.0f;
        #pragma unroll
        for (int nt = 0; nt < 8; ++nt) {
            const int cc = col0 + warp_n * 64 + nt * 8 + (lane & 3) * 2;
            float v0 = acc[mt][nt][0], v1 = acc[mt][nt][1];
            float v2 = acc[mt][nt][2], v3 = acc[mt][nt][3];
            if (sec == 0) {
                v0 = 1.0f / (1.0f + expf(-v0));
                v1 = 1.0f / (1.0f + expf(-v1));
                v2 = 1.0f / (1.0f + expf(-v2));
                v3 = 1.0f / (1.0f + expf(-v3));
            } else if (sec == 1) {
                v0 = tanhf(v0) * m0;
                v1 = tanhf(v1) * m0;
                v2 = tanhf(v2) * m1;
                v3 = tanhf(v3) * m1;
            }
            *reinterpret_cast<float2*>(g_qkv + (size_t)r0 * TDq + cc) = make_float2(v0, v1);
            *reinterpret_cast<float2*>(g_qkv + (size_t)r1 * TDq + cc) = make_float2(v2, v3);
        }
    }
}

// ---------------------------------------------------------------------------
// Kernel 4a: zero kv accumulator (graph replays every launch).
// ---------------------------------------------------------------------------
__global__ void zero_kv() {
    const int i = blockIdx.x * blockDim.x + threadIdx.x;
    if (i < Bq * Hq * HDq * HDq) g_kv[i] = 0.f;
}

// ---------------------------------------------------------------------------
// Kernel 4b: kv[b,h] = sum_n k^T v, split-K over N with fp32 atomics.
// ---------------------------------------------------------------------------
__global__ __launch_bounds__(256, 2)
void kv_gemm() {
    __shared__ float ks[8][128];
    __shared__ float vs[8][128];
    const int bh = blockIdx.x;
    const int split = blockIdx.y;
    const int b = bh >> 3, h = bh & 7;
    const int tid = threadIdx.x;
    const int tx = tid & 15, ty = tid >> 4;
    const int lr = tid >> 5;
    const int lc = (tid & 31) * 4;

    const int nchunk = Nq / KV_SPLIT;
    const int n0 = split * nchunk;
    const float* kbase = g_qkv + (size_t)(b * Nq + n0 + lr) * TDq + Dq + h * HDq + lc;
    const float* vbase = kbase + Dq;

    float acc[8][8];
    #pragma unroll
    for (int i = 0; i < 8; i++)
        #pragma unroll
        for (int j = 0; j < 8; j++) acc[i][j] = 0.f;

    for (int nn = 0; nn < nchunk; nn += 8) {
        const float4 kv4 = *reinterpret_cast<const float4*>(kbase + (size_t)nn * TDq);
        const float4 vv4 = *reinterpret_cast<const float4*>(vbase + (size_t)nn * TDq);
        *reinterpret_cast<float4*>(&ks[lr][lc]) = kv4;
        *reinterpret_cast<float4*>(&vs[lr][lc]) = vv4;
        __syncthreads();
        #pragma unroll
        for (int kk = 0; kk < 8; kk++) {
            float a[8], c[8];
            #pragma unroll
            for (int i = 0; i < 8; i++) a[i] = ks[kk][ty * 8 + i];
            #pragma unroll
            for (int j = 0; j < 8; j++) c[j] = vs[kk][tx * 8 + j];
            #pragma unroll
            for (int i = 0; i < 8; i++)
                #pragma unroll
                for (int j = 0; j < 8; j++) acc[i][j] += a[i] * c[j];
        }
        __syncthreads();
    }

    float* out = g_kv + (size_t)bh * HDq * HDq;
    #pragma unroll
    for (int i = 0; i < 8; i++)
        #pragma unroll
        for (int j = 0; j < 8; j++)
            atomicAdd(&out[(ty * 8 + i) * HDq + tx * 8 + j], acc[i][j]);
}

// ---------------------------------------------------------------------------
// Kernel 5: out[b,h] = q[b,h] @ kv[b,h].
// ---------------------------------------------------------------------------
__global__ __launch_bounds__(256, 2)
void out_gemm(float* __restrict__ out) {
    __shared__ float qs[8][128];
    __shared__ float cs[8][128];
    const int bh = blockIdx.y;
    const int b = bh >> 3, h = bh & 7;
    const int n0 = blockIdx.x * 128;
    const int tid = threadIdx.x;
    const int tx = tid & 15, ty = tid >> 4;
    const int ar = tid >> 1, ac = (tid & 1) * 4;
    const int br = tid >> 5, bc = (tid & 31) * 4;

    const float* qptr  = g_qkv + (size_t)(b * Nq + n0 + ar) * TDq + h * HDq + ac;
    const float* kvptr = g_kv + ((size_t)bh * HDq + br) * HDq + bc;

    float acc[8][8];
    #pragma unroll
    for (int i = 0; i < 8; i++)
        #pragma unroll
        for (int j = 0; j < 8; j++) acc[i][j] = 0.f;

    for (int k0 = 0; k0 < HDq; k0 += 8) {
        const float4 qv = *reinterpret_cast<const float4*>(qptr + k0);
        const float4 cv = *reinterpret_cast<const float4*>(kvptr + (size_t)k0 * HDq);
        qs[ac + 0][ar] = qv.x; qs[ac + 1][ar] = qv.y;
        qs[ac + 2][ar] = qv.z; qs[ac + 3][ar] = qv.w;
        *reinterpret_cast<float4*>(&cs[br][bc]) = cv;
        __syncthreads();
        #pragma unroll
        for (int kk = 0; kk < 8; kk++) {
            float a[8], c[8];
            #pragma unroll
            for (int i = 0; i < 8; i++) a[i] = qs[kk][ty * 8 + i];
            #pragma unroll
            for (int j = 0; j < 8; j++) c[j] = cs[kk][tx * 8 + j];
            #pragma unroll
            for (int i = 0; i < 8; i++)
                #pragma unroll
                for (int j = 0; j < 8; j++) acc[i][j] += a[i] * c[j];
        }
        __syncthreads();
    }

    #pragma unroll
    for (int i = 0; i < 8; i++) {
        const int n = n0 + ty * 8 + i;
        float* op = out + (size_t)(b * Nq + n) * Dq + h * HDq + tx * 8;
        #pragma unroll
        for (int j = 0; j < 8; j++) op[j] = acc[i][j];
    }
}

// ---------------------------------------------------------------------------
// Launch: inputs in metadata order: x, mask, w_qkv, gamma, beta.
// ---------------------------------------------------------------------------
extern "C" void kernel_launch(void* const* d_in, const int* in_sizes, int n_in,
                              void* d_out, int out_size) {
    const float* x     = (const float*)d_in[0];
    const void*  mask  = d_in[1];
    const float* w     = (const float*)d_in[2];
    const float* gamma = (const float*)d_in[3];
    const float* beta  = (const float*)d_in[4];
    float* out         = (float*)d_out;

    static int smem_set = 0;
    if (!smem_set) {
        cudaFuncSetAttribute(mma_qkv_gemm,
                             cudaFuncAttributeMaxDynamicSharedMemorySize, QKV_SMEM);
        smem_set = 1;
    }

    mask_detect<<<1, 256>>>((const int*)mask);
    mask_expand<<<(Bq * Nq + 255) / 256, 256>>>(mask);
    ln_split<<<Bq * Nq, 256>>>(x, gamma, beta);
    w_split<<<dim3(TDq / 32, Dq / 32), dim3(32, 8)>>>(w);
    mma_qkv_gemm<<<dim3(TDq / 128, (Bq * Nq) / 128), 256, QKV_SMEM>>>();
    zero_kv<<<(Bq * Hq * HDq * HDq + 255) / 256, 256>>>();
    kv_gemm<<<dim3(Bq * Hq, KV_SPLIT), 256>>>();
    out_gemm<<<dim3(Nq / 128, Bq * Hq), 256>>>(out);
}

// round 6
// speedup vs baseline: 3.1070x; 1.9344x over previous
#include <cuda_runtime.h>
#include <cuda_fp16.h>
#include <math.h>
#include <stdint.h>

#define Bq 4
#define Nq 8192
#define Dq 1024
#define Hq 8
#define HDq 128
#define TDq 3072
#define KV_SPLIT 16

// ---------------------------------------------------------------------------
// Device scratch.
// ---------------------------------------------------------------------------
__device__ __align__(16) __half g_xh[(size_t)Bq * Nq * Dq];   // LN(x) fp16 hi
__device__ __align__(16) __half g_xl[(size_t)Bq * Nq * Dq];   // LN(x) fp16 lo
__device__ __align__(16) __half g_wth[(size_t)TDq * Dq];      // W^T fp16 hi [3072,1024]
__device__ __align__(16) float g_qkv[(size_t)Bq * Nq * TDq];  // activated q|k|v (f32)
__device__ __align__(16) float g_kv[(size_t)Bq * Hq * HDq * HDq];
__device__ float g_maskf[(size_t)Bq * Nq];
__device__ int   g_mask_is_i32;

// ---------------------------------------------------------------------------
// PTX helpers (sm_80-level: mma.sync / ldmatrix / cp.async — compile for
// base compute_103; tcgen05 does NOT, per R4 ptxas evidence).
// ---------------------------------------------------------------------------
__device__ __forceinline__ uint32_t smem_u32(const void* p) {
    uint32_t a;
    asm("{ .reg .u64 t; cvta.to.shared.u64 t, %1; cvt.u32.u64 %0, t; }" : "=r"(a) : "l"(p));
    return a;
}
#define CP_ASYNC16(saddr, gptr) \
    asm volatile("cp.async.cg.shared.global [%0], [%1], 16;" :: "r"(saddr), "l"(gptr))
#define CP_COMMIT() asm volatile("cp.async.commit_group;" ::: "memory")
#define CP_WAIT(n)  asm volatile("cp.async.wait_group %0;" :: "n"(n) : "memory")

#define LDSM4(R0, R1, R2, R3, addr) \
    asm volatile("ldmatrix.sync.aligned.m8n8.x4.shared.b16 {%0,%1,%2,%3}, [%4];" \
                 : "=r"(R0), "=r"(R1), "=r"(R2), "=r"(R3) : "r"(addr))

#define MMAF16(d, a0, a1, a2, a3, b0, b1) \
    asm volatile("mma.sync.aligned.m16n8k16.row.col.f32.f16.f16.f32 " \
                 "{%0,%1,%2,%3}, {%4,%5,%6,%7}, {%8,%9}, {%0,%1,%2,%3};" \
                 : "+f"((d)[0]), "+f"((d)[1]), "+f"((d)[2]), "+f"((d)[3]) \
                 : "r"(a0), "r"(a1), "r"(a2), "r"(a3), "r"(b0), "r"(b1))

// ---------------------------------------------------------------------------
// Kernel 0a/0b: mask dtype detect + canonicalize.
// ---------------------------------------------------------------------------
__global__ void mask_detect(const int* __restrict__ m) {
    __shared__ int bad[8];
    int mybad = 0;
    for (int i = threadIdx.x; i < 4096; i += blockDim.x) {
        const int v = m[i];
        if (v != 0 && v != 1) mybad = 1;
    }
    #pragma unroll
    for (int o = 16; o > 0; o >>= 1) mybad |= __shfl_down_sync(0xffffffffu, mybad, o);
    if ((threadIdx.x & 31) == 0) bad[threadIdx.x >> 5] = mybad;
    __syncthreads();
    if (threadIdx.x == 0) {
        int t = 0;
        #pragma unroll
        for (int i = 0; i < 8; i++) t |= bad[i];
        g_mask_is_i32 = t ? 0 : 1;
    }
}
__global__ void mask_expand(const void* __restrict__ m) {
    const int i = blockIdx.x * blockDim.x + threadIdx.x;
    if (i >= Bq * Nq) return;
    int set;
    if (g_mask_is_i32) set = ((const int*)m)[i] != 0;
    else               set = ((const unsigned char*)m)[i] != 0;
    g_maskf[i] = set ? 0.0f : 1.0f;
}

// ---------------------------------------------------------------------------
// Kernel 1: LayerNorm + fp16 hi/lo split.
// ---------------------------------------------------------------------------
__device__ __forceinline__ void hsplit(float v, __half& h, __half& l) {
    h = __float2half_rn(v);
    l = __float2half_rn(v - __half2float(h));
}
__global__ void ln_split(const float* __restrict__ x,
                         const float* __restrict__ gamma,
                         const float* __restrict__ beta) {
    const int row = blockIdx.x;
    const int t = threadIdx.x;
    const float4 a = reinterpret_cast<const float4*>(x + (size_t)row * Dq)[t];
    float s  = a.x + a.y + a.z + a.w;
    float ss = a.x * a.x + a.y * a.y + a.z * a.z + a.w * a.w;

    __shared__ float red[16];
    __shared__ float mv[2];
    #pragma unroll
    for (int o = 16; o > 0; o >>= 1) {
        s  += __shfl_down_sync(0xffffffffu, s, o);
        ss += __shfl_down_sync(0xffffffffu, ss, o);
    }
    const int w = t >> 5, l = t & 31;
    if (l == 0) { red[w] = s; red[w + 8] = ss; }
    __syncthreads();
    if (t == 0) {
        float ts = 0.f, tss = 0.f;
        #pragma unroll
        for (int i = 0; i < 8; i++) { ts += red[i]; tss += red[i + 8]; }
        const float mean = ts * (1.0f / Dq);
        const float var  = tss * (1.0f / Dq) - mean * mean;
        mv[0] = mean;
        mv[1] = rsqrtf(var + 1e-5f);
    }
    __syncthreads();
    const float mean = mv[0], rstd = mv[1];
    const float4 g4 = reinterpret_cast<const float4*>(gamma)[t];
    const float4 b4 = reinterpret_cast<const float4*>(beta)[t];
    float o0 = (a.x - mean) * rstd * g4.x + b4.x;
    float o1 = (a.y - mean) * rstd * g4.y + b4.y;
    float o2 = (a.z - mean) * rstd * g4.z + b4.z;
    float o3 = (a.w - mean) * rstd * g4.w + b4.w;
    __half h0, h1, h2, h3, l0, l1, l2, l3;
    hsplit(o0, h0, l0); hsplit(o1, h1, l1); hsplit(o2, h2, l2); hsplit(o3, h3, l3);
    const size_t idx = (size_t)row * Dq + t * 4;
    *reinterpret_cast<__half2*>(g_xh + idx)     = __halves2half2(h0, h1);
    *reinterpret_cast<__half2*>(g_xh + idx + 2) = __halves2half2(h2, h3);
    *reinterpret_cast<__half2*>(g_xl + idx)     = __halves2half2(l0, l1);
    *reinterpret_cast<__half2*>(g_xl + idx + 2) = __halves2half2(l2, l3);
}

// ---------------------------------------------------------------------------
// Kernel 2: W [1024,3072] fp32 -> W^T [3072,1024] fp16 (hi only).
// ---------------------------------------------------------------------------
__global__ void w_split(const float* __restrict__ W) {
    __shared__ float tile[32][33];
    const int n0 = blockIdx.x * 32;
    const int k0 = blockIdx.y * 32;
    const int tx = threadIdx.x, ty = threadIdx.y;
    #pragma unroll
    for (int j = 0; j < 4; j++)
        tile[ty + 8 * j][tx] = W[(size_t)(k0 + ty + 8 * j) * TDq + n0 + tx];
    __syncthreads();
    #pragma unroll
    for (int j = 0; j < 4; j++) {
        const float v = tile[tx][ty + 8 * j];
        g_wth[(size_t)(n0 + ty + 8 * j) * Dq + k0 + tx] = __float2half_rn(v);
    }
}

// ---------------------------------------------------------------------------
// Kernel 3: HMMA QKV GEMM, fp16x2 split (Ah*Bh + Al*Bh), fused activations.
// 128x128 tile, BK=64 (128B rows, u^(r&7) swizzle), 4-stage cp.async,
// 8 warps (4m x 2n), 256 threads, 1 CTA/SM (192KB smem).
// ---------------------------------------------------------------------------
#define TILE_B   16384          // one 128x64 fp16 tile = 128 rows * 128B
#define STAGE_B  (3 * TILE_B)   // Ah, Al, Bh
#define NSTAGE   4
#define QKV_SMEM (NSTAGE * STAGE_B)

__device__ __forceinline__ uint32_t swz(int r, int u) {  // byte offset in tile
    return (uint32_t)(r * 128 + ((u ^ (r & 7)) << 4));
}

__global__ __launch_bounds__(256, 1) void mma_qkv_gemm() {
    extern __shared__ char smem[];
    const uint32_t su = smem_u32(smem);
    const int tid = threadIdx.x;
    const int lane = tid & 31;
    const int wid = tid >> 5;
    const int warp_m = wid & 3;          // 0..3 -> 32 rows each
    const int warp_n = wid >> 2;         // 0..1 -> 64 cols each
    const int row0 = blockIdx.y * 128;
    const int col0 = blockIdx.x * 128;

    const char* gsrc0 = (const char*)g_xh  + (size_t)row0 * 2048;
    const char* gsrc1 = (const char*)g_xl  + (size_t)row0 * 2048;
    const char* gsrc2 = (const char*)g_wth + (size_t)col0 * 2048;

    auto load_stage = [&](int s, int c) {
        const uint32_t sb = su + s * STAGE_B;
        const size_t kb = (size_t)c * 128;       // byte offset along K
        #pragma unroll
        for (int i = 0; i < 4; ++i) {
            const int w = tid + i * 256;         // 0..1023 (16B units of one tile)
            const int r = w >> 3;
            const int u = w & 7;
            const uint32_t so = swz(r, u);
            const size_t go = (size_t)r * 2048 + kb + (size_t)u * 16;
            CP_ASYNC16(sb + 0 * TILE_B + so, gsrc0 + go);
            CP_ASYNC16(sb + 1 * TILE_B + so, gsrc1 + go);
            CP_ASYNC16(sb + 2 * TILE_B + so, gsrc2 + go);
        }
    };

    float acc[2][8][4];
    #pragma unroll
    for (int mt = 0; mt < 2; mt++)
        #pragma unroll
        for (int nt = 0; nt < 8; nt++)
            #pragma unroll
            for (int k = 0; k < 4; k++) acc[mt][nt][k] = 0.f;

    load_stage(0, 0); CP_COMMIT();
    load_stage(1, 1); CP_COMMIT();
    load_stage(2, 2); CP_COMMIT();

    for (int c = 0; c < 16; ++c) {
        if (c + 3 < 16) {
            load_stage((c + 3) % NSTAGE, c + 3); CP_COMMIT();
            CP_WAIT(3);
        } else if (c + 2 < 16) {
            CP_WAIT(2);
        } else if (c + 1 < 16) {
            CP_WAIT(1);
        } else {
            CP_WAIT(0);
        }
        __syncthreads();

        const uint32_t sb = su + (c % NSTAGE) * STAGE_B;
        #pragma unroll
        for (int kk = 0; kk < 4; ++kk) {
            uint32_t ah[2][4], al[2][4];
            #pragma unroll
            for (int mt = 0; mt < 2; ++mt) {
                const int r = warp_m * 32 + mt * 16 + (lane & 15);
                const int u = kk * 2 + (lane >> 4);
                const uint32_t so = swz(r, u);
                LDSM4(ah[mt][0], ah[mt][1], ah[mt][2], ah[mt][3], sb + 0 * TILE_B + so);
                LDSM4(al[mt][0], al[mt][1], al[mt][2], al[mt][3], sb + 1 * TILE_B + so);
            }
            uint32_t bh[4][4];
            #pragma unroll
            for (int p = 0; p < 4; ++p) {
                const int rn = warp_n * 64 + p * 16 + (lane & 7) + ((lane >> 4) & 1) * 8;
                const int u = kk * 2 + ((lane >> 3) & 1);
                const uint32_t so = swz(rn, u);
                LDSM4(bh[p][0], bh[p][1], bh[p][2], bh[p][3], sb + 2 * TILE_B + so);
            }
            #pragma unroll
            for (int mt = 0; mt < 2; ++mt)
                #pragma unroll
                for (int p = 0; p < 4; ++p) {
                    MMAF16(acc[mt][2 * p],     ah[mt][0], ah[mt][1], ah[mt][2], ah[mt][3], bh[p][0], bh[p][1]);
                    MMAF16(acc[mt][2 * p + 1], ah[mt][0], ah[mt][1], ah[mt][2], ah[mt][3], bh[p][2], bh[p][3]);
                    MMAF16(acc[mt][2 * p],     al[mt][0], al[mt][1], al[mt][2], al[mt][3], bh[p][0], bh[p][1]);
                    MMAF16(acc[mt][2 * p + 1], al[mt][0], al[mt][1], al[mt][2], al[mt][3], bh[p][2], bh[p][3]);
                }
        }
        __syncthreads();
    }

    // -------- epilogue: activation + store --------------------------------
    const int sec = blockIdx.x >> 3;     // 0=q, 1=k, 2=v (block-uniform)
    #pragma unroll
    for (int mt = 0; mt < 2; ++mt) {
        const int r0 = row0 + warp_m * 32 + mt * 16 + (lane >> 2);
        const int r1 = r0 + 8;
        const float m0 = (sec == 1) ? g_maskf[r0] : 1.0f;
        const float m1 = (sec == 1) ? g_maskf[r1] : 1.0f;
        #pragma unroll
        for (int nt = 0; nt < 8; ++nt) {
            const int cc = col0 + warp_n * 64 + nt * 8 + (lane & 3) * 2;
            float v0 = acc[mt][nt][0], v1 = acc[mt][nt][1];
            float v2 = acc[mt][nt][2], v3 = acc[mt][nt][3];
            if (sec == 0) {
                v0 = 1.0f / (1.0f + expf(-v0));
                v1 = 1.0f / (1.0f + expf(-v1));
                v2 = 1.0f / (1.0f + expf(-v2));
                v3 = 1.0f / (1.0f + expf(-v3));
            } else if (sec == 1) {
                v0 = tanhf(v0) * m0;
                v1 = tanhf(v1) * m0;
                v2 = tanhf(v2) * m1;
                v3 = tanhf(v3) * m1;
            }
            *reinterpret_cast<float2*>(g_qkv + (size_t)r0 * TDq + cc) = make_float2(v0, v1);
            *reinterpret_cast<float2*>(g_qkv + (size_t)r1 * TDq + cc) = make_float2(v2, v3);
        }
    }
}

// ---------------------------------------------------------------------------
// Kernel 4a: zero kv accumulator (graph replays every launch).
// ---------------------------------------------------------------------------
__global__ void zero_kv() {
    const int i = blockIdx.x * blockDim.x + threadIdx.x;
    if (i < Bq * Hq * HDq * HDq) g_kv[i] = 0.f;
}

// ---------------------------------------------------------------------------
// Kernel 4b: kv[b,h] = sum_n k^T v, split-K over N with fp32 atomics.
// ---------------------------------------------------------------------------
__global__ __launch_bounds__(256, 2)
void kv_gemm() {
    __shared__ float ks[8][128];
    __shared__ float vs[8][128];
    const int bh = blockIdx.x;
    const int split = blockIdx.y;
    const int b = bh >> 3, h = bh & 7;
    const int tid = threadIdx.x;
    const int tx = tid & 15, ty = tid >> 4;
    const int lr = tid >> 5;
    const int lc = (tid & 31) * 4;

    const int nchunk = Nq / KV_SPLIT;
    const int n0 = split * nchunk;
    const float* kbase = g_qkv + (size_t)(b * Nq + n0 + lr) * TDq + Dq + h * HDq + lc;
    const float* vbase = kbase + Dq;

    float acc[8][8];
    #pragma unroll
    for (int i = 0; i < 8; i++)
        #pragma unroll
        for (int j = 0; j < 8; j++) acc[i][j] = 0.f;

    for (int nn = 0; nn < nchunk; nn += 8) {
        const float4 kv4 = *reinterpret_cast<const float4*>(kbase + (size_t)nn * TDq);
        const float4 vv4 = *reinterpret_cast<const float4*>(vbase + (size_t)nn * TDq);
        *reinterpret_cast<float4*>(&ks[lr][lc]) = kv4;
        *reinterpret_cast<float4*>(&vs[lr][lc]) = vv4;
        __syncthreads();
        #pragma unroll
        for (int kk = 0; kk < 8; kk++) {
            float a[8], c[8];
            #pragma unroll
            for (int i = 0; i < 8; i++) a[i] = ks[kk][ty * 8 + i];
            #pragma unroll
            for (int j = 0; j < 8; j++) c[j] = vs[kk][tx * 8 + j];
            #pragma unroll
            for (int i = 0; i < 8; i++)
                #pragma unroll
                for (int j = 0; j < 8; j++) acc[i][j] += a[i] * c[j];
        }
        __syncthreads();
    }

    float* out = g_kv + (size_t)bh * HDq * HDq;
    #pragma unroll
    for (int i = 0; i < 8; i++)
        #pragma unroll
        for (int j = 0; j < 8; j++)
            atomicAdd(&out[(ty * 8 + i) * HDq + tx * 8 + j], acc[i][j]);
}

// ---------------------------------------------------------------------------
// Kernel 5: out[b,h] = q[b,h] @ kv[b,h].
// ---------------------------------------------------------------------------
__global__ __launch_bounds__(256, 2)
void out_gemm(float* __restrict__ out) {
    __shared__ float qs[8][128];
    __shared__ float cs[8][128];
    const int bh = blockIdx.y;
    const int b = bh >> 3, h = bh & 7;
    const int n0 = blockIdx.x * 128;
    const int tid = threadIdx.x;
    const int tx = tid & 15, ty = tid >> 4;
    const int ar = tid >> 1, ac = (tid & 1) * 4;
    const int br = tid >> 5, bc = (tid & 31) * 4;

    const float* qptr  = g_qkv + (size_t)(b * Nq + n0 + ar) * TDq + h * HDq + ac;
    const float* kvptr = g_kv + ((size_t)bh * HDq + br) * HDq + bc;

    float acc[8][8];
    #pragma unroll
    for (int i = 0; i < 8; i++)
        #pragma unroll
        for (int j = 0; j < 8; j++) acc[i][j] = 0.f;

    for (int k0 = 0; k0 < HDq; k0 += 8) {
        const float4 qv = *reinterpret_cast<const float4*>(qptr + k0);
        const float4 cv = *reinterpret_cast<const float4*>(kvptr + (size_t)k0 * HDq);
        qs[ac + 0][ar] = qv.x; qs[ac + 1][ar] = qv.y;
        qs[ac + 2][ar] = qv.z; qs[ac + 3][ar] = qv.w;
        *reinterpret_cast<float4*>(&cs[br][bc]) = cv;
        __syncthreads();
        #pragma unroll
        for (int kk = 0; kk < 8; kk++) {
            float a[8], c[8];
            #pragma unroll
            for (int i = 0; i < 8; i++) a[i] = qs[kk][ty * 8 + i];
            #pragma unroll
            for (int j = 0; j < 8; j++) c[j] = cs[kk][tx * 8 + j];
            #pragma unroll
            for (int i = 0; i < 8; i++)
                #pragma unroll
                for (int j = 0; j < 8; j++) acc[i][j] += a[i] * c[j];
        }
        __syncthreads();
    }

    #pragma unroll
    for (int i = 0; i < 8; i++) {
        const int n = n0 + ty * 8 + i;
        float* op = out + (size_t)(b * Nq + n) * Dq + h * HDq + tx * 8;
        #pragma unroll
        for (int j = 0; j < 8; j++) op[j] = acc[i][j];
    }
}

// ---------------------------------------------------------------------------
// Launch: inputs in metadata order: x, mask, w_qkv, gamma, beta.
// ---------------------------------------------------------------------------
extern "C" void kernel_launch(void* const* d_in, const int* in_sizes, int n_in,
                              void* d_out, int out_size) {
    const float* x     = (const float*)d_in[0];
    const void*  mask  = d_in[1];
    const float* w     = (const float*)d_in[2];
    const float* gamma = (const float*)d_in[3];
    const float* beta  = (const float*)d_in[4];
    float* out         = (float*)d_out;

    static int smem_set = 0;
    if (!smem_set) {
        cudaFuncSetAttribute(mma_qkv_gemm,
                             cudaFuncAttributeMaxDynamicSharedMemorySize, QKV_SMEM);
        smem_set = 1;
    }

    mask_detect<<<1, 256>>>((const int*)mask);
    mask_expand<<<(Bq * Nq + 255) / 256, 256>>>(mask);
    ln_split<<<Bq * Nq, 256>>>(x, gamma, beta);
    w_split<<<dim3(TDq / 32, Dq / 32), dim3(32, 8)>>>(w);
    mma_qkv_gemm<<<dim3(TDq / 128, (Bq * Nq) / 128), 256, QKV_SMEM>>>();
    zero_kv<<<(Bq * Hq * HDq * HDq + 255) / 256, 256>>>();
    kv_gemm<<<dim3(Bq * Hq, KV_SPLIT), 256>>>();
    out_gemm<<<dim3(Nq / 128, Bq * Hq), 256>>>(out);
}

// round 8
// speedup vs baseline: 4.0055x; 1.2892x over previous
#include <cuda_runtime.h>
#include <cuda_fp16.h>
#include <math.h>
#include <stdint.h>

#define Bq 4
#define Nq 8192
#define Dq 1024
#define Hq 8
#define HDq 128
#define TDq 3072
#define KV_SPLIT 16

// ---------------------------------------------------------------------------
// Device scratch.
// ---------------------------------------------------------------------------
__device__ __align__(16) __half g_xh[(size_t)Bq * Nq * Dq];   // LN(x) fp16 hi
__device__ __align__(16) __half g_xl[(size_t)Bq * Nq * Dq];   // LN(x) fp16 lo
__device__ __align__(16) __half g_wth[(size_t)TDq * Dq];      // W^T fp16 [3072,1024]
__device__ __align__(16) __half g_qh[(size_t)Bq * Nq * Dq];   // sigmoid(q) hi/lo
__device__ __align__(16) __half g_ql[(size_t)Bq * Nq * Dq];
__device__ __align__(16) __half g_kh[(size_t)Bq * Nq * Dq];   // tanh(k)*mask hi/lo
__device__ __align__(16) __half g_kl[(size_t)Bq * Nq * Dq];
__device__ __align__(16) __half g_vh[(size_t)Bq * Nq * Dq];   // v hi/lo
__device__ __align__(16) __half g_vl[(size_t)Bq * Nq * Dq];
__device__ __align__(16) float g_kv[(size_t)Bq * Hq * HDq * HDq];
__device__ float g_maskf[(size_t)Bq * Nq];
__device__ int   g_mask_is_i32;

// ---------------------------------------------------------------------------
// PTX helpers (sm_80-level; tcgen05 rejected by base compute_103, per R4).
// ---------------------------------------------------------------------------
__device__ __forceinline__ uint32_t smem_u32(const void* p) {
    uint32_t a;
    asm("{ .reg .u64 t; cvta.to.shared.u64 t, %1; cvt.u32.u64 %0, t; }" : "=r"(a) : "l"(p));
    return a;
}
#define CP_ASYNC16(saddr, gptr) \
    asm volatile("cp.async.cg.shared.global [%0], [%1], 16;" :: "r"(saddr), "l"(gptr))
#define CP_COMMIT() asm volatile("cp.async.commit_group;" ::: "memory")
#define CP_WAIT(n)  asm volatile("cp.async.wait_group %0;" :: "n"(n) : "memory")

#define LDSM4(R0, R1, R2, R3, addr) \
    asm volatile("ldmatrix.sync.aligned.m8n8.x4.shared.b16 {%0,%1,%2,%3}, [%4];" \
                 : "=r"(R0), "=r"(R1), "=r"(R2), "=r"(R3) : "r"(addr))
#define LDSM4T(R0, R1, R2, R3, addr) \
    asm volatile("ldmatrix.sync.aligned.m8n8.x4.trans.shared.b16 {%0,%1,%2,%3}, [%4];" \
                 : "=r"(R0), "=r"(R1), "=r"(R2), "=r"(R3) : "r"(addr))

#define MMAF16(d, a0, a1, a2, a3, b0, b1) \
    asm volatile("mma.sync.aligned.m16n8k16.row.col.f32.f16.f16.f32 " \
                 "{%0,%1,%2,%3}, {%4,%5,%6,%7}, {%8,%9}, {%0,%1,%2,%3};" \
                 : "+f"((d)[0]), "+f"((d)[1]), "+f"((d)[2]), "+f"((d)[3]) \
                 : "r"(a0), "r"(a1), "r"(a2), "r"(a3), "r"(b0), "r"(b1))

// swizzles: 128B rows (qkv gemm) and 256B rows (head-sliced fp16 tiles)
__device__ __forceinline__ uint32_t swz(int r, int u) {
    return (uint32_t)(r * 128 + ((u ^ (r & 7)) << 4));
}
__device__ __forceinline__ uint32_t swz256(int r, int u) {
    return (uint32_t)(r * 256 + ((u ^ ((r & 7) << 1)) << 4));
}

__device__ __forceinline__ void hsplit(float v, __half& h, __half& l) {
    h = __float2half_rn(v);
    l = __float2half_rn(v - __half2float(h));
}

// ---------------------------------------------------------------------------
// Kernel 0a/0b: mask dtype detect + canonicalize.
// ---------------------------------------------------------------------------
__global__ void mask_detect(const int* __restrict__ m) {
    __shared__ int bad[8];
    int mybad = 0;
    for (int i = threadIdx.x; i < 4096; i += blockDim.x) {
        const int v = m[i];
        if (v != 0 && v != 1) mybad = 1;
    }
    #pragma unroll
    for (int o = 16; o > 0; o >>= 1) mybad |= __shfl_down_sync(0xffffffffu, mybad, o);
    if ((threadIdx.x & 31) == 0) bad[threadIdx.x >> 5] = mybad;
    __syncthreads();
    if (threadIdx.x == 0) {
        int t = 0;
        #pragma unroll
        for (int i = 0; i < 8; i++) t |= bad[i];
        g_mask_is_i32 = t ? 0 : 1;
    }
}
__global__ void mask_expand(const void* __restrict__ m) {
    const int i = blockIdx.x * blockDim.x + threadIdx.x;
    if (i >= Bq * Nq) return;
    int set;
    if (g_mask_is_i32) set = ((const int*)m)[i] != 0;
    else               set = ((const unsigned char*)m)[i] != 0;
    g_maskf[i] = set ? 0.0f : 1.0f;
}

// ---------------------------------------------------------------------------
// Kernel 1: LayerNorm + fp16 hi/lo split.
// ---------------------------------------------------------------------------
__global__ void ln_split(const float* __restrict__ x,
                         const float* __restrict__ gamma,
                         const float* __restrict__ beta) {
    const int row = blockIdx.x;
    const int t = threadIdx.x;
    const float4 a = reinterpret_cast<const float4*>(x + (size_t)row * Dq)[t];
    float s  = a.x + a.y + a.z + a.w;
    float ss = a.x * a.x + a.y * a.y + a.z * a.z + a.w * a.w;

    __shared__ float red[16];
    __shared__ float mv[2];
    #pragma unroll
    for (int o = 16; o > 0; o >>= 1) {
        s  += __shfl_down_sync(0xffffffffu, s, o);
        ss += __shfl_down_sync(0xffffffffu, ss, o);
    }
    const int w = t >> 5, l = t & 31;
    if (l == 0) { red[w] = s; red[w + 8] = ss; }
    __syncthreads();
    if (t == 0) {
        float ts = 0.f, tss = 0.f;
        #pragma unroll
        for (int i = 0; i < 8; i++) { ts += red[i]; tss += red[i + 8]; }
        const float mean = ts * (1.0f / Dq);
        const float var  = tss * (1.0f / Dq) - mean * mean;
        mv[0] = mean;
        mv[1] = rsqrtf(var + 1e-5f);
    }
    __syncthreads();
    const float mean = mv[0], rstd = mv[1];
    const float4 g4 = reinterpret_cast<const float4*>(gamma)[t];
    const float4 b4 = reinterpret_cast<const float4*>(beta)[t];
    float o0 = (a.x - mean) * rstd * g4.x + b4.x;
    float o1 = (a.y - mean) * rstd * g4.y + b4.y;
    float o2 = (a.z - mean) * rstd * g4.z + b4.z;
    float o3 = (a.w - mean) * rstd * g4.w + b4.w;
    __half h0, h1, h2, h3, l0, l1, l2, l3;
    hsplit(o0, h0, l0); hsplit(o1, h1, l1); hsplit(o2, h2, l2); hsplit(o3, h3, l3);
    const size_t idx = (size_t)row * Dq + t * 4;
    *reinterpret_cast<__half2*>(g_xh + idx)     = __halves2half2(h0, h1);
    *reinterpret_cast<__half2*>(g_xh + idx + 2) = __halves2half2(h2, h3);
    *reinterpret_cast<__half2*>(g_xl + idx)     = __halves2half2(l0, l1);
    *reinterpret_cast<__half2*>(g_xl + idx + 2) = __halves2half2(l2, l3);
}

// ---------------------------------------------------------------------------
// Kernel 2: W [1024,3072] fp32 -> W^T [3072,1024] fp16.
// ---------------------------------------------------------------------------
__global__ void w_split(const float* __restrict__ W) {
    __shared__ float tile[32][33];
    const int n0 = blockIdx.x * 32;
    const int k0 = blockIdx.y * 32;
    const int tx = threadIdx.x, ty = threadIdx.y;
    #pragma unroll
    for (int j = 0; j < 4; j++)
        tile[ty + 8 * j][tx] = W[(size_t)(k0 + ty + 8 * j) * TDq + n0 + tx];
    __syncthreads();
    #pragma unroll
    for (int j = 0; j < 4; j++) {
        const float v = tile[tx][ty + 8 * j];
        g_wth[(size_t)(n0 + ty + 8 * j) * Dq + k0 + tx] = __float2half_rn(v);
    }
}

// ---------------------------------------------------------------------------
// Kernel 3: HMMA QKV GEMM, fp16x2 split, epilogue -> fp16 hi/lo q/k/v.
// ---------------------------------------------------------------------------
#define TILE_B   16384
#define STAGE_B  (3 * TILE_B)   // Ah, Al, Bh
#define NSTAGE   4
#define QKV_SMEM (NSTAGE * STAGE_B)

__global__ __launch_bounds__(256, 1) void mma_qkv_gemm() {
    extern __shared__ char smem[];
    const uint32_t su = smem_u32(smem);
    const int tid = threadIdx.x;
    const int lane = tid & 31;
    const int wid = tid >> 5;
    const int warp_m = wid & 3;
    const int warp_n = wid >> 2;
    const int row0 = blockIdx.y * 128;
    const int col0 = blockIdx.x * 128;

    const char* gsrc0 = (const char*)g_xh  + (size_t)row0 * 2048;
    const char* gsrc1 = (const char*)g_xl  + (size_t)row0 * 2048;
    const char* gsrc2 = (const char*)g_wth + (size_t)col0 * 2048;

    auto load_stage = [&](int s, int c) {
        const uint32_t sb = su + s * STAGE_B;
        const size_t kb = (size_t)c * 128;
        #pragma unroll
        for (int i = 0; i < 4; ++i) {
            const int w = tid + i * 256;
            const int r = w >> 3;
            const int u = w & 7;
            const uint32_t so = swz(r, u);
            const size_t go = (size_t)r * 2048 + kb + (size_t)u * 16;
            CP_ASYNC16(sb + 0 * TILE_B + so, gsrc0 + go);
            CP_ASYNC16(sb + 1 * TILE_B + so, gsrc1 + go);
            CP_ASYNC16(sb + 2 * TILE_B + so, gsrc2 + go);
        }
    };

    float acc[2][8][4];
    #pragma unroll
    for (int mt = 0; mt < 2; mt++)
        #pragma unroll
        for (int nt = 0; nt < 8; nt++)
            #pragma unroll
            for (int k = 0; k < 4; k++) acc[mt][nt][k] = 0.f;

    load_stage(0, 0); CP_COMMIT();
    load_stage(1, 1); CP_COMMIT();
    load_stage(2, 2); CP_COMMIT();

    for (int c = 0; c < 16; ++c) {
        if (c + 3 < 16) {
            load_stage((c + 3) % NSTAGE, c + 3); CP_COMMIT();
            CP_WAIT(3);
        } else if (c + 2 < 16) {
            CP_WAIT(2);
        } else if (c + 1 < 16) {
            CP_WAIT(1);
        } else {
            CP_WAIT(0);
        }
        __syncthreads();

        const uint32_t sb = su + (c % NSTAGE) * STAGE_B;
        #pragma unroll
        for (int kk = 0; kk < 4; ++kk) {
            uint32_t ah[2][4], al[2][4];
            #pragma unroll
            for (int mt = 0; mt < 2; ++mt) {
                const int r = warp_m * 32 + mt * 16 + (lane & 15);
                const int u = kk * 2 + (lane >> 4);
                const uint32_t so = swz(r, u);
                LDSM4(ah[mt][0], ah[mt][1], ah[mt][2], ah[mt][3], sb + 0 * TILE_B + so);
                LDSM4(al[mt][0], al[mt][1], al[mt][2], al[mt][3], sb + 1 * TILE_B + so);
            }
            #pragma unroll
            for (int p = 0; p < 4; ++p) {
                uint32_t bh0, bh1, bh2, bh3;
                const int rn = warp_n * 64 + p * 16 + (lane & 7) + ((lane >> 4) & 1) * 8;
                const int u = kk * 2 + ((lane >> 3) & 1);
                const uint32_t so = swz(rn, u);
                LDSM4(bh0, bh1, bh2, bh3, sb + 2 * TILE_B + so);
                #pragma unroll
                for (int mt = 0; mt < 2; ++mt) {
                    MMAF16(acc[mt][2 * p],     ah[mt][0], ah[mt][1], ah[mt][2], ah[mt][3], bh0, bh1);
                    MMAF16(acc[mt][2 * p + 1], ah[mt][0], ah[mt][1], ah[mt][2], ah[mt][3], bh2, bh3);
                    MMAF16(acc[mt][2 * p],     al[mt][0], al[mt][1], al[mt][2], al[mt][3], bh0, bh1);
                    MMAF16(acc[mt][2 * p + 1], al[mt][0], al[mt][1], al[mt][2], al[mt][3], bh2, bh3);
                }
            }
        }
        __syncthreads();
    }

    // epilogue: activation + fp16 hi/lo store into section arrays
    const int sec = blockIdx.x >> 3;     // 0=q, 1=k, 2=v
    __half* dh = (sec == 0) ? g_qh : (sec == 1) ? g_kh : g_vh;
    __half* dl = (sec == 0) ? g_ql : (sec == 1) ? g_kl : g_vl;
    const int csec0 = col0 - sec * Dq;   // column within the section [0,1024)
    #pragma unroll
    for (int mt = 0; mt < 2; ++mt) {
        const int r0 = row0 + warp_m * 32 + mt * 16 + (lane >> 2);
        const int r1 = r0 + 8;
        const float m0 = (sec == 1) ? g_maskf[r0] : 1.0f;
        const float m1 = (sec == 1) ? g_maskf[r1] : 1.0f;
        #pragma unroll
        for (int nt = 0; nt < 8; ++nt) {
            const int cc = csec0 + warp_n * 64 + nt * 8 + (lane & 3) * 2;
            float v0 = acc[mt][nt][0], v1 = acc[mt][nt][1];
            float v2 = acc[mt][nt][2], v3 = acc[mt][nt][3];
            if (sec == 0) {
                v0 = 1.0f / (1.0f + expf(-v0));
                v1 = 1.0f / (1.0f + expf(-v1));
                v2 = 1.0f / (1.0f + expf(-v2));
                v3 = 1.0f / (1.0f + expf(-v3));
            } else if (sec == 1) {
                v0 = tanhf(v0) * m0;
                v1 = tanhf(v1) * m0;
                v2 = tanhf(v2) * m1;
                v3 = tanhf(v3) * m1;
            }
            __half h0, h1, h2, h3, l0, l1, l2, l3;
            hsplit(v0, h0, l0); hsplit(v1, h1, l1);
            hsplit(v2, h2, l2); hsplit(v3, h3, l3);
            *reinterpret_cast<__half2*>(dh + (size_t)r0 * Dq + cc) = __halves2half2(h0, h1);
            *reinterpret_cast<__half2*>(dl + (size_t)r0 * Dq + cc) = __halves2half2(l0, l1);
            *reinterpret_cast<__half2*>(dh + (size_t)r1 * Dq + cc) = __halves2half2(h2, h3);
            *reinterpret_cast<__half2*>(dl + (size_t)r1 * Dq + cc) = __halves2half2(l2, l3);
        }
    }
}

// ---------------------------------------------------------------------------
// Kernel 4a: zero kv accumulator.
// ---------------------------------------------------------------------------
__global__ void zero_kv() {
    const int i = blockIdx.x * blockDim.x + threadIdx.x;
    if (i < Bq * Hq * HDq * HDq) g_kv[i] = 0.f;
}

// ---------------------------------------------------------------------------
// Kernel 4b: kv[b,h][d][e] = sum_n k[n][d] v[n][e].  HMMA, trans loads.
// 3-stage ring => prefetch 2, issue chunk c+2 into (c+2)%3 (freed at c-1),
// CP_WAIT(2). (R7 bug: issuing c+3 into c%3 clobbered the consuming stage.)
// ---------------------------------------------------------------------------
#define KVT_B    8192           // 32 rows * 256B
#define KVSTG_B  (4 * KVT_B)    // kh, kl, vh, vl
#define KV_SMEM  (3 * KVSTG_B)  // 96KB

__global__ __launch_bounds__(256, 2) void mma_kv_gemm() {
    extern __shared__ char smem[];
    const uint32_t su = smem_u32(smem);
    const int tid = threadIdx.x;
    const int lane = tid & 31;
    const int wid = tid >> 5;
    const int warp_m = wid & 3;          // d tile: 32 rows
    const int warp_n = wid >> 2;         // e tile: 64 cols
    const int bh = blockIdx.x;           // 0..31
    const int split = blockIdx.y;        // 0..15
    const int b = bh >> 3, h = bh & 7;
    const int n0 = split * (Nq / KV_SPLIT);

    const char* gkh = (const char*)g_kh + ((size_t)(b * Nq + n0) * Dq + h * HDq) * 2;
    const char* gkl = (const char*)g_kl + ((size_t)(b * Nq + n0) * Dq + h * HDq) * 2;
    const char* gvh = (const char*)g_vh + ((size_t)(b * Nq + n0) * Dq + h * HDq) * 2;
    const char* gvl = (const char*)g_vl + ((size_t)(b * Nq + n0) * Dq + h * HDq) * 2;

    auto load_stage = [&](int s, int c) {
        const uint32_t sb = su + s * KVSTG_B;
        #pragma unroll
        for (int i = 0; i < 2; ++i) {
            const int w = tid + i * 256;     // 0..511 = 32 rows * 16 units
            const int r = w >> 4;
            const int u = w & 15;
            const uint32_t so = swz256(r, u);
            const size_t go = (size_t)(c * 32 + r) * 2048 + (size_t)u * 16;
            CP_ASYNC16(sb + 0 * KVT_B + so, gkh + go);
            CP_ASYNC16(sb + 1 * KVT_B + so, gkl + go);
            CP_ASYNC16(sb + 2 * KVT_B + so, gvh + go);
            CP_ASYNC16(sb + 3 * KVT_B + so, gvl + go);
        }
    };

    float acc[2][8][4];
    #pragma unroll
    for (int mt = 0; mt < 2; mt++)
        #pragma unroll
        for (int nt = 0; nt < 8; nt++)
            #pragma unroll
            for (int k = 0; k < 4; k++) acc[mt][nt][k] = 0.f;

    load_stage(0, 0); CP_COMMIT();
    load_stage(1, 1); CP_COMMIT();

    const int NC = 16;                   // 512 n / 32
    for (int c = 0; c < NC; ++c) {
        if (c + 2 < NC) {
            load_stage((c + 2) % 3, c + 2); CP_COMMIT();
            CP_WAIT(2);
        } else if (c + 1 < NC) {
            CP_WAIT(1);
        } else {
            CP_WAIT(0);
        }
        __syncthreads();

        const uint32_t sb = su + (c % 3) * KVSTG_B;
        #pragma unroll
        for (int kk = 0; kk < 2; ++kk) {       // 2 x 16 n per stage
            uint32_t ah[2][4], al[2][4];
            #pragma unroll
            for (int mt = 0; mt < 2; ++mt) {
                const int m0 = warp_m * 32 + mt * 16;          // d
                const int kr = kk * 16 + (lane & 7) + ((lane >> 4) & 1) * 8;   // n row
                const int mu = (m0 >> 3) + ((lane >> 3) & 1);  // 16B unit along d
                const uint32_t so = swz256(kr, mu);
                LDSM4T(ah[mt][0], ah[mt][1], ah[mt][2], ah[mt][3], sb + 0 * KVT_B + so);
                LDSM4T(al[mt][0], al[mt][1], al[mt][2], al[mt][3], sb + 1 * KVT_B + so);
            }
            #pragma unroll
            for (int p = 0; p < 4; ++p) {
                const int e0 = warp_n * 64 + p * 16;
                const int kr = kk * 16 + (lane & 7) + ((lane >> 3) & 1) * 8;
                const int eu = (e0 >> 3) + ((lane >> 4) & 1);
                const uint32_t so = swz256(kr, eu);
                uint32_t bh0, bh1, bh2, bh3, bl0, bl1, bl2, bl3;
                LDSM4T(bh0, bh1, bh2, bh3, sb + 2 * KVT_B + so);
                LDSM4T(bl0, bl1, bl2, bl3, sb + 3 * KVT_B + so);
                #pragma unroll
                for (int mt = 0; mt < 2; ++mt) {
                    MMAF16(acc[mt][2 * p],     ah[mt][0], ah[mt][1], ah[mt][2], ah[mt][3], bh0, bh1);
                    MMAF16(acc[mt][2 * p + 1], ah[mt][0], ah[mt][1], ah[mt][2], ah[mt][3], bh2, bh3);
                    MMAF16(acc[mt][2 * p],     ah[mt][0], ah[mt][1], ah[mt][2], ah[mt][3], bl0, bl1);
                    MMAF16(acc[mt][2 * p + 1], ah[mt][0], ah[mt][1], ah[mt][2], ah[mt][3], bl2, bl3);
                    MMAF16(acc[mt][2 * p],     al[mt][0], al[mt][1], al[mt][2], al[mt][3], bh0, bh1);
                    MMAF16(acc[mt][2 * p + 1], al[mt][0], al[mt][1], al[mt][2], al[mt][3], bh2, bh3);
                }
            }
        }
        __syncthreads();
    }

    float* outp = g_kv + (size_t)bh * HDq * HDq;
    #pragma unroll
    for (int mt = 0; mt < 2; ++mt) {
        const int d0 = warp_m * 32 + mt * 16 + (lane >> 2);
        const int d1 = d0 + 8;
        #pragma unroll
        for (int nt = 0; nt < 8; ++nt) {
            const int e = warp_n * 64 + nt * 8 + (lane & 3) * 2;
            atomicAdd(&outp[d0 * HDq + e],     acc[mt][nt][0]);
            atomicAdd(&outp[d0 * HDq + e + 1], acc[mt][nt][1]);
            atomicAdd(&outp[d1 * HDq + e],     acc[mt][nt][2]);
            atomicAdd(&outp[d1 * HDq + e + 1], acc[mt][nt][3]);
        }
    }
}

// ---------------------------------------------------------------------------
// Kernel 5: out[n][e] = sum_d q[n][d] kv[d][e].  HMMA.
// ---------------------------------------------------------------------------
#define OUT_QT_B  (128 * 256)
#define OUT_SMEM  (4 * OUT_QT_B)   // 128KB: qh, ql, kvh, kvl

__global__ __launch_bounds__(256, 1) void mma_out_gemm(float* __restrict__ out) {
    extern __shared__ char smem[];
    const uint32_t su = smem_u32(smem);
    const int tid = threadIdx.x;
    const int lane = tid & 31;
    const int wid = tid >> 5;
    const int warp_m = wid & 3;
    const int warp_n = wid >> 2;
    const int n0 = blockIdx.x * 128;
    const int bh = blockIdx.y;
    const int b = bh >> 3, h = bh & 7;

    const char* gqh = (const char*)g_qh + ((size_t)(b * Nq + n0) * Dq + h * HDq) * 2;
    const char* gql = (const char*)g_ql + ((size_t)(b * Nq + n0) * Dq + h * HDq) * 2;

    #pragma unroll
    for (int i = 0; i < 8; ++i) {
        const int w = tid + i * 256;         // 0..2047 = 128 rows * 16 units
        const int r = w >> 4;
        const int u = w & 15;
        const uint32_t so = swz256(r, u);
        const size_t go = (size_t)r * 2048 + (size_t)u * 16;
        CP_ASYNC16(su + 0 * OUT_QT_B + so, gqh + go);
        CP_ASYNC16(su + 1 * OUT_QT_B + so, gql + go);
    }
    CP_COMMIT();

    // convert kv f32 -> fp16 hi/lo into swizzled smem
    {
        const float* kvp = g_kv + (size_t)bh * HDq * HDq;
        __half* s_kvh = (__half*)(smem + 2 * OUT_QT_B);
        __half* s_kvl = (__half*)(smem + 3 * OUT_QT_B);
        #pragma unroll
        for (int i = 0; i < 64; ++i) {
            const int idx = tid + i * 256;   // 0..16383
            const int d = idx >> 7, e = idx & 127;
            const float v = kvp[idx];
            __half hh, hl;
            hsplit(v, hh, hl);
            const uint32_t off = swz256(d, e >> 3) + (e & 7) * 2;
            *reinterpret_cast<__half*>((char*)s_kvh + off) = hh;
            *reinterpret_cast<__half*>((char*)s_kvl + off) = hl;
        }
    }
    CP_WAIT(0);
    __syncthreads();

    float acc[2][8][4];
    #pragma unroll
    for (int mt = 0; mt < 2; mt++)
        #pragma unroll
        for (int nt = 0; nt < 8; nt++)
            #pragma unroll
            for (int k = 0; k < 4; k++) acc[mt][nt][k] = 0.f;

    #pragma unroll
    for (int kk = 0; kk < 8; ++kk) {         // K = d = 128
        uint32_t ah[2][4], al[2][4];
        #pragma unroll
        for (int mt = 0; mt < 2; ++mt) {
            const int r = warp_m * 32 + mt * 16 + (lane & 15);
            const int u = kk * 2 + (lane >> 4);
            const uint32_t so = swz256(r, u);
            LDSM4(ah[mt][0], ah[mt][1], ah[mt][2], ah[mt][3], su + 0 * OUT_QT_B + so);
            LDSM4(al[mt][0], al[mt][1], al[mt][2], al[mt][3], su + 1 * OUT_QT_B + so);
        }
        #pragma unroll
        for (int p = 0; p < 4; ++p) {
            const int e0 = warp_n * 64 + p * 16;
            const int kr = kk * 16 + (lane & 7) + ((lane >> 3) & 1) * 8;   // d row
            const int eu = (e0 >> 3) + ((lane >> 4) & 1);
            const uint32_t so = swz256(kr, eu);
            uint32_t bh0, bh1, bh2, bh3, bl0, bl1, bl2, bl3;
            LDSM4T(bh0, bh1, bh2, bh3, su + 2 * OUT_QT_B + so);
            LDSM4T(bl0, bl1, bl2, bl3, su + 3 * OUT_QT_B + so);
            #pragma unroll
            for (int mt = 0; mt < 2; ++mt) {
                MMAF16(acc[mt][2 * p],     ah[mt][0], ah[mt][1], ah[mt][2], ah[mt][3], bh0, bh1);
                MMAF16(acc[mt][2 * p + 1], ah[mt][0], ah[mt][1], ah[mt][2], ah[mt][3], bh2, bh3);
                MMAF16(acc[mt][2 * p],     ah[mt][0], ah[mt][1], ah[mt][2], ah[mt][3], bl0, bl1);
                MMAF16(acc[mt][2 * p + 1], ah[mt][0], ah[mt][1], ah[mt][2], ah[mt][3], bl2, bl3);
                MMAF16(acc[mt][2 * p],     al[mt][0], al[mt][1], al[mt][2], al[mt][3], bh0, bh1);
                MMAF16(acc[mt][2 * p + 1], al[mt][0], al[mt][1], al[mt][2], al[mt][3], bh2, bh3);
            }
        }
    }

    #pragma unroll
    for (int mt = 0; mt < 2; ++mt) {
        const int r0 = n0 + warp_m * 32 + mt * 16 + (lane >> 2);
        const int r1 = r0 + 8;
        #pragma unroll
        for (int nt = 0; nt < 8; ++nt) {
            const int e = warp_n * 64 + nt * 8 + (lane & 3) * 2;
            float* o0 = out + (size_t)(b * Nq + r0) * Dq + h * HDq + e;
            float* o1 = out + (size_t)(b * Nq + r1) * Dq + h * HDq + e;
            *reinterpret_cast<float2*>(o0) = make_float2(acc[mt][nt][0], acc[mt][nt][1]);
            *reinterpret_cast<float2*>(o1) = make_float2(acc[mt][nt][2], acc[mt][nt][3]);
        }
    }
}

// ---------------------------------------------------------------------------
// Launch: inputs in metadata order: x, mask, w_qkv, gamma, beta.
// ---------------------------------------------------------------------------
extern "C" void kernel_launch(void* const* d_in, const int* in_sizes, int n_in,
                              void* d_out, int out_size) {
    const float* x     = (const float*)d_in[0];
    const void*  mask  = d_in[1];
    const float* w     = (const float*)d_in[2];
    const float* gamma = (const float*)d_in[3];
    const float* beta  = (const float*)d_in[4];
    float* out         = (float*)d_out;

    static int smem_set = 0;
    if (!smem_set) {
        cudaFuncSetAttribute(mma_qkv_gemm, cudaFuncAttributeMaxDynamicSharedMemorySize, QKV_SMEM);
        cudaFuncSetAttribute(mma_kv_gemm,  cudaFuncAttributeMaxDynamicSharedMemorySize, KV_SMEM);
        cudaFuncSetAttribute(mma_out_gemm, cudaFuncAttributeMaxDynamicSharedMemorySize, OUT_SMEM);
        smem_set = 1;
    }

    mask_detect<<<1, 256>>>((const int*)mask);
    mask_expand<<<(Bq * Nq + 255) / 256, 256>>>(mask);
    ln_split<<<Bq * Nq, 256>>>(x, gamma, beta);
    w_split<<<dim3(TDq / 32, Dq / 32), dim3(32, 8)>>>(w);
    mma_qkv_gemm<<<dim3(TDq / 128, (Bq * Nq) / 128), 256, QKV_SMEM>>>();
    zero_kv<<<(Bq * Hq * HDq * HDq + 255) / 256, 256>>>();
    mma_kv_gemm<<<dim3(Bq * Hq, KV_SPLIT), 256, KV_SMEM>>>();
    mma_out_gemm<<<dim3(Nq / 128, Bq * Hq), 256, OUT_SMEM>>>(out);
}

// round 9
// speedup vs baseline: 5.4284x; 1.3552x over previous
#include <cuda_runtime.h>
#include <cuda_fp16.h>
#include <math.h>
#include <stdint.h>

#define Bq 4
#define Nq 8192
#define Dq 1024
#define Hq 8
#define HDq 128
#define TDq 3072
#define KV_SPLIT 16

// ---------------------------------------------------------------------------
// Device scratch.
// ---------------------------------------------------------------------------
__device__ __align__(16) __half g_xh[(size_t)Bq * Nq * Dq];   // LN(x) fp16
__device__ __align__(16) __half g_wth[(size_t)TDq * Dq];      // W^T fp16 [3072,1024]
__device__ __align__(16) __half g_qh[(size_t)Bq * Nq * Dq];   // sigmoid(q) hi/lo
__device__ __align__(16) __half g_ql[(size_t)Bq * Nq * Dq];
__device__ __align__(16) __half g_kh[(size_t)Bq * Nq * Dq];   // tanh(k)*mask hi/lo
__device__ __align__(16) __half g_kl[(size_t)Bq * Nq * Dq];
__device__ __align__(16) __half g_vh[(size_t)Bq * Nq * Dq];   // v hi/lo
__device__ __align__(16) __half g_vl[(size_t)Bq * Nq * Dq];
__device__ __align__(16) float g_kv[(size_t)Bq * Hq * HDq * HDq];
__device__ float g_maskf[(size_t)Bq * Nq];
__device__ int   g_mask_is_i32;

// ---------------------------------------------------------------------------
// PTX helpers (sm_80-level; tcgen05 rejected by base compute_103, per R4).
// ---------------------------------------------------------------------------
__device__ __forceinline__ uint32_t smem_u32(const void* p) {
    uint32_t a;
    asm("{ .reg .u64 t; cvta.to.shared.u64 t, %1; cvt.u32.u64 %0, t; }" : "=r"(a) : "l"(p));
    return a;
}
#define CP_ASYNC16(saddr, gptr) \
    asm volatile("cp.async.cg.shared.global [%0], [%1], 16;" :: "r"(saddr), "l"(gptr))
#define CP_COMMIT() asm volatile("cp.async.commit_group;" ::: "memory")
#define CP_WAIT(n)  asm volatile("cp.async.wait_group %0;" :: "n"(n) : "memory")

#define LDSM4(R0, R1, R2, R3, addr) \
    asm volatile("ldmatrix.sync.aligned.m8n8.x4.shared.b16 {%0,%1,%2,%3}, [%4];" \
                 : "=r"(R0), "=r"(R1), "=r"(R2), "=r"(R3) : "r"(addr))
#define LDSM4T(R0, R1, R2, R3, addr) \
    asm volatile("ldmatrix.sync.aligned.m8n8.x4.trans.shared.b16 {%0,%1,%2,%3}, [%4];" \
                 : "=r"(R0), "=r"(R1), "=r"(R2), "=r"(R3) : "r"(addr))

#define MMAF16(d, a0, a1, a2, a3, b0, b1) \
    asm volatile("mma.sync.aligned.m16n8k16.row.col.f32.f16.f16.f32 " \
                 "{%0,%1,%2,%3}, {%4,%5,%6,%7}, {%8,%9}, {%0,%1,%2,%3};" \
                 : "+f"((d)[0]), "+f"((d)[1]), "+f"((d)[2]), "+f"((d)[3]) \
                 : "r"(a0), "r"(a1), "r"(a2), "r"(a3), "r"(b0), "r"(b1))

// swizzles: 128B rows (qkv gemm) and 256B rows (head-sliced fp16 tiles)
__device__ __forceinline__ uint32_t swz(int r, int u) {
    return (uint32_t)(r * 128 + ((u ^ (r & 7)) << 4));
}
__device__ __forceinline__ uint32_t swz256(int r, int u) {
    return (uint32_t)(r * 256 + ((u ^ ((r & 7) << 1)) << 4));
}

__device__ __forceinline__ void hsplit(float v, __half& h, __half& l) {
    h = __float2half_rn(v);
    l = __float2half_rn(v - __half2float(h));
}

// ---------------------------------------------------------------------------
// Kernel 0a/0b: mask dtype detect + canonicalize.
// ---------------------------------------------------------------------------
__global__ void mask_detect(const int* __restrict__ m) {
    __shared__ int bad[8];
    int mybad = 0;
    for (int i = threadIdx.x; i < 4096; i += blockDim.x) {
        const int v = m[i];
        if (v != 0 && v != 1) mybad = 1;
    }
    #pragma unroll
    for (int o = 16; o > 0; o >>= 1) mybad |= __shfl_down_sync(0xffffffffu, mybad, o);
    if ((threadIdx.x & 31) == 0) bad[threadIdx.x >> 5] = mybad;
    __syncthreads();
    if (threadIdx.x == 0) {
        int t = 0;
        #pragma unroll
        for (int i = 0; i < 8; i++) t |= bad[i];
        g_mask_is_i32 = t ? 0 : 1;
    }
}
__global__ void mask_expand(const void* __restrict__ m) {
    const int i = blockIdx.x * blockDim.x + threadIdx.x;
    if (i >= Bq * Nq) return;
    int set;
    if (g_mask_is_i32) set = ((const int*)m)[i] != 0;
    else               set = ((const unsigned char*)m)[i] != 0;
    g_maskf[i] = set ? 0.0f : 1.0f;
}

// ---------------------------------------------------------------------------
// Kernel 1: LayerNorm -> fp16 (single term; xl no longer needed).
// ---------------------------------------------------------------------------
__global__ void ln_split(const float* __restrict__ x,
                         const float* __restrict__ gamma,
                         const float* __restrict__ beta) {
    const int row = blockIdx.x;
    const int t = threadIdx.x;
    const float4 a = reinterpret_cast<const float4*>(x + (size_t)row * Dq)[t];
    float s  = a.x + a.y + a.z + a.w;
    float ss = a.x * a.x + a.y * a.y + a.z * a.z + a.w * a.w;

    __shared__ float red[16];
    __shared__ float mv[2];
    #pragma unroll
    for (int o = 16; o > 0; o >>= 1) {
        s  += __shfl_down_sync(0xffffffffu, s, o);
        ss += __shfl_down_sync(0xffffffffu, ss, o);
    }
    const int w = t >> 5, l = t & 31;
    if (l == 0) { red[w] = s; red[w + 8] = ss; }
    __syncthreads();
    if (t == 0) {
        float ts = 0.f, tss = 0.f;
        #pragma unroll
        for (int i = 0; i < 8; i++) { ts += red[i]; tss += red[i + 8]; }
        const float mean = ts * (1.0f / Dq);
        const float var  = tss * (1.0f / Dq) - mean * mean;
        mv[0] = mean;
        mv[1] = rsqrtf(var + 1e-5f);
    }
    __syncthreads();
    const float mean = mv[0], rstd = mv[1];
    const float4 g4 = reinterpret_cast<const float4*>(gamma)[t];
    const float4 b4 = reinterpret_cast<const float4*>(beta)[t];
    const float o0 = (a.x - mean) * rstd * g4.x + b4.x;
    const float o1 = (a.y - mean) * rstd * g4.y + b4.y;
    const float o2 = (a.z - mean) * rstd * g4.z + b4.z;
    const float o3 = (a.w - mean) * rstd * g4.w + b4.w;
    const size_t idx = (size_t)row * Dq + t * 4;
    *reinterpret_cast<__half2*>(g_xh + idx) =
        __halves2half2(__float2half_rn(o0), __float2half_rn(o1));
    *reinterpret_cast<__half2*>(g_xh + idx + 2) =
        __halves2half2(__float2half_rn(o2), __float2half_rn(o3));
}

// ---------------------------------------------------------------------------
// Kernel 2: W [1024,3072] fp32 -> W^T [3072,1024] fp16.
// ---------------------------------------------------------------------------
__global__ void w_split(const float* __restrict__ W) {
    __shared__ float tile[32][33];
    const int n0 = blockIdx.x * 32;
    const int k0 = blockIdx.y * 32;
    const int tx = threadIdx.x, ty = threadIdx.y;
    #pragma unroll
    for (int j = 0; j < 4; j++)
        tile[ty + 8 * j][tx] = W[(size_t)(k0 + ty + 8 * j) * TDq + n0 + tx];
    __syncthreads();
    #pragma unroll
    for (int j = 0; j < 4; j++) {
        const float v = tile[tx][ty + 8 * j];
        g_wth[(size_t)(n0 + ty + 8 * j) * Dq + k0 + tx] = __float2half_rn(v);
    }
}

// ---------------------------------------------------------------------------
// Kernel 3: HMMA QKV GEMM, single fp16 term, 6-stage cp.async pipeline.
// 128x128 tile, BK=64; epilogue -> fp16 hi/lo q/k/v for downstream HMMA.
// ---------------------------------------------------------------------------
#define TILE_B   16384
#define STAGE_B  (2 * TILE_B)   // Ah, Bh
#define NSTAGE   6
#define QKV_SMEM (NSTAGE * STAGE_B)   // 192KB

__global__ __launch_bounds__(256, 1) void mma_qkv_gemm() {
    extern __shared__ char smem[];
    const uint32_t su = smem_u32(smem);
    const int tid = threadIdx.x;
    const int lane = tid & 31;
    const int wid = tid >> 5;
    const int warp_m = wid & 3;
    const int warp_n = wid >> 2;
    const int row0 = blockIdx.y * 128;
    const int col0 = blockIdx.x * 128;

    const char* gsrc0 = (const char*)g_xh  + (size_t)row0 * 2048;
    const char* gsrc2 = (const char*)g_wth + (size_t)col0 * 2048;

    auto load_stage = [&](int s, int c) {
        const uint32_t sb = su + s * STAGE_B;
        const size_t kb = (size_t)c * 128;
        #pragma unroll
        for (int i = 0; i < 4; ++i) {
            const int w = tid + i * 256;
            const int r = w >> 3;
            const int u = w & 7;
            const uint32_t so = swz(r, u);
            const size_t go = (size_t)r * 2048 + kb + (size_t)u * 16;
            CP_ASYNC16(sb + 0 * TILE_B + so, gsrc0 + go);
            CP_ASYNC16(sb + 1 * TILE_B + so, gsrc2 + go);
        }
    };

    float acc[2][8][4];
    #pragma unroll
    for (int mt = 0; mt < 2; mt++)
        #pragma unroll
        for (int nt = 0; nt < 8; nt++)
            #pragma unroll
            for (int k = 0; k < 4; k++) acc[mt][nt][k] = 0.f;

    load_stage(0, 0); CP_COMMIT();
    load_stage(1, 1); CP_COMMIT();
    load_stage(2, 2); CP_COMMIT();
    load_stage(3, 3); CP_COMMIT();
    load_stage(4, 4); CP_COMMIT();

    for (int c = 0; c < 16; ++c) {
        if (c + 5 < 16) {
            load_stage((c + 5) % NSTAGE, c + 5); CP_COMMIT();
            CP_WAIT(5);
        } else if (c + 4 < 16) {
            CP_WAIT(4);
        } else if (c + 3 < 16) {
            CP_WAIT(3);
        } else if (c + 2 < 16) {
            CP_WAIT(2);
        } else if (c + 1 < 16) {
            CP_WAIT(1);
        } else {
            CP_WAIT(0);
        }
        __syncthreads();

        const uint32_t sb = su + (c % NSTAGE) * STAGE_B;
        #pragma unroll
        for (int kk = 0; kk < 4; ++kk) {
            uint32_t ah[2][4];
            #pragma unroll
            for (int mt = 0; mt < 2; ++mt) {
                const int r = warp_m * 32 + mt * 16 + (lane & 15);
                const int u = kk * 2 + (lane >> 4);
                const uint32_t so = swz(r, u);
                LDSM4(ah[mt][0], ah[mt][1], ah[mt][2], ah[mt][3], sb + 0 * TILE_B + so);
            }
            #pragma unroll
            for (int p = 0; p < 4; ++p) {
                uint32_t bh0, bh1, bh2, bh3;
                const int rn = warp_n * 64 + p * 16 + (lane & 7) + ((lane >> 4) & 1) * 8;
                const int u = kk * 2 + ((lane >> 3) & 1);
                const uint32_t so = swz(rn, u);
                LDSM4(bh0, bh1, bh2, bh3, sb + 1 * TILE_B + so);
                #pragma unroll
                for (int mt = 0; mt < 2; ++mt) {
                    MMAF16(acc[mt][2 * p],     ah[mt][0], ah[mt][1], ah[mt][2], ah[mt][3], bh0, bh1);
                    MMAF16(acc[mt][2 * p + 1], ah[mt][0], ah[mt][1], ah[mt][2], ah[mt][3], bh2, bh3);
                }
            }
        }
        __syncthreads();
    }

    // epilogue: activation + fp16 hi/lo store into section arrays
    const int sec = blockIdx.x >> 3;     // 0=q, 1=k, 2=v
    __half* dh = (sec == 0) ? g_qh : (sec == 1) ? g_kh : g_vh;
    __half* dl = (sec == 0) ? g_ql : (sec == 1) ? g_kl : g_vl;
    const int csec0 = col0 - sec * Dq;   // column within the section [0,1024)
    #pragma unroll
    for (int mt = 0; mt < 2; ++mt) {
        const int r0 = row0 + warp_m * 32 + mt * 16 + (lane >> 2);
        const int r1 = r0 + 8;
        const float m0 = (sec == 1) ? g_maskf[r0] : 1.0f;
        const float m1 = (sec == 1) ? g_maskf[r1] : 1.0f;
        #pragma unroll
        for (int nt = 0; nt < 8; ++nt) {
            const int cc = csec0 + warp_n * 64 + nt * 8 + (lane & 3) * 2;
            float v0 = acc[mt][nt][0], v1 = acc[mt][nt][1];
            float v2 = acc[mt][nt][2], v3 = acc[mt][nt][3];
            if (sec == 0) {
                v0 = 1.0f / (1.0f + expf(-v0));
                v1 = 1.0f / (1.0f + expf(-v1));
                v2 = 1.0f / (1.0f + expf(-v2));
                v3 = 1.0f / (1.0f + expf(-v3));
            } else if (sec == 1) {
                v0 = tanhf(v0) * m0;
                v1 = tanhf(v1) * m0;
                v2 = tanhf(v2) * m1;
                v3 = tanhf(v3) * m1;
            }
            __half h0, h1, h2, h3, l0, l1, l2, l3;
            hsplit(v0, h0, l0); hsplit(v1, h1, l1);
            hsplit(v2, h2, l2); hsplit(v3, h3, l3);
            *reinterpret_cast<__half2*>(dh + (size_t)r0 * Dq + cc) = __halves2half2(h0, h1);
            *reinterpret_cast<__half2*>(dl + (size_t)r0 * Dq + cc) = __halves2half2(l0, l1);
            *reinterpret_cast<__half2*>(dh + (size_t)r1 * Dq + cc) = __halves2half2(h2, h3);
            *reinterpret_cast<__half2*>(dl + (size_t)r1 * Dq + cc) = __halves2half2(l2, l3);
        }
    }
}

// ---------------------------------------------------------------------------
// Kernel 4a: zero kv accumulator.
// ---------------------------------------------------------------------------
__global__ void zero_kv() {
    const int i = blockIdx.x * blockDim.x + threadIdx.x;
    if (i < Bq * Hq * HDq * HDq) g_kv[i] = 0.f;
}

// ---------------------------------------------------------------------------
// Kernel 4b: kv[b,h][d][e] = sum_n k[n][d] v[n][e].  HMMA, trans loads,
// 3-term split, 3-stage ring (prefetch 2 — R8-validated schedule).
// ---------------------------------------------------------------------------
#define KVT_B    8192           // 32 rows * 256B
#define KVSTG_B  (4 * KVT_B)    // kh, kl, vh, vl
#define KV_SMEM  (3 * KVSTG_B)  // 96KB

__global__ __launch_bounds__(256, 2) void mma_kv_gemm() {
    extern __shared__ char smem[];
    const uint32_t su = smem_u32(smem);
    const int tid = threadIdx.x;
    const int lane = tid & 31;
    const int wid = tid >> 5;
    const int warp_m = wid & 3;          // d tile: 32 rows
    const int warp_n = wid >> 2;         // e tile: 64 cols
    const int bh = blockIdx.x;           // 0..31
    const int split = blockIdx.y;        // 0..15
    const int b = bh >> 3, h = bh & 7;
    const int n0 = split * (Nq / KV_SPLIT);

    const char* gkh = (const char*)g_kh + ((size_t)(b * Nq + n0) * Dq + h * HDq) * 2;
    const char* gkl = (const char*)g_kl + ((size_t)(b * Nq + n0) * Dq + h * HDq) * 2;
    const char* gvh = (const char*)g_vh + ((size_t)(b * Nq + n0) * Dq + h * HDq) * 2;
    const char* gvl = (const char*)g_vl + ((size_t)(b * Nq + n0) * Dq + h * HDq) * 2;

    auto load_stage = [&](int s, int c) {
        const uint32_t sb = su + s * KVSTG_B;
        #pragma unroll
        for (int i = 0; i < 2; ++i) {
            const int w = tid + i * 256;     // 0..511 = 32 rows * 16 units
            const int r = w >> 4;
            const int u = w & 15;
            const uint32_t so = swz256(r, u);
            const size_t go = (size_t)(c * 32 + r) * 2048 + (size_t)u * 16;
            CP_ASYNC16(sb + 0 * KVT_B + so, gkh + go);
            CP_ASYNC16(sb + 1 * KVT_B + so, gkl + go);
            CP_ASYNC16(sb + 2 * KVT_B + so, gvh + go);
            CP_ASYNC16(sb + 3 * KVT_B + so, gvl + go);
        }
    };

    float acc[2][8][4];
    #pragma unroll
    for (int mt = 0; mt < 2; mt++)
        #pragma unroll
        for (int nt = 0; nt < 8; nt++)
            #pragma unroll
            for (int k = 0; k < 4; k++) acc[mt][nt][k] = 0.f;

    load_stage(0, 0); CP_COMMIT();
    load_stage(1, 1); CP_COMMIT();

    const int NC = 16;                   // 512 n / 32
    for (int c = 0; c < NC; ++c) {
        if (c + 2 < NC) {
            load_stage((c + 2) % 3, c + 2); CP_COMMIT();
            CP_WAIT(2);
        } else if (c + 1 < NC) {
            CP_WAIT(1);
        } else {
            CP_WAIT(0);
        }
        __syncthreads();

        const uint32_t sb = su + (c % 3) * KVSTG_B;
        #pragma unroll
        for (int kk = 0; kk < 2; ++kk) {       // 2 x 16 n per stage
            uint32_t ah[2][4], al[2][4];
            #pragma unroll
            for (int mt = 0; mt < 2; ++mt) {
                const int m0 = warp_m * 32 + mt * 16;          // d
                const int kr = kk * 16 + (lane & 7) + ((lane >> 4) & 1) * 8;   // n row
                const int mu = (m0 >> 3) + ((lane >> 3) & 1);  // 16B unit along d
                const uint32_t so = swz256(kr, mu);
                LDSM4T(ah[mt][0], ah[mt][1], ah[mt][2], ah[mt][3], sb + 0 * KVT_B + so);
                LDSM4T(al[mt][0], al[mt][1], al[mt][2], al[mt][3], sb + 1 * KVT_B + so);
            }
            #pragma unroll
            for (int p = 0; p < 4; ++p) {
                const int e0 = warp_n * 64 + p * 16;
                const int kr = kk * 16 + (lane & 7) + ((lane >> 3) & 1) * 8;
                const int eu = (e0 >> 3) + ((lane >> 4) & 1);
                const uint32_t so = swz256(kr, eu);
                uint32_t bh0, bh1, bh2, bh3, bl0, bl1, bl2, bl3;
                LDSM4T(bh0, bh1, bh2, bh3, sb + 2 * KVT_B + so);
                LDSM4T(bl0, bl1, bl2, bl3, sb + 3 * KVT_B + so);
                #pragma unroll
                for (int mt = 0; mt < 2; ++mt) {
                    MMAF16(acc[mt][2 * p],     ah[mt][0], ah[mt][1], ah[mt][2], ah[mt][3], bh0, bh1);
                    MMAF16(acc[mt][2 * p + 1], ah[mt][0], ah[mt][1], ah[mt][2], ah[mt][3], bh2, bh3);
                    MMAF16(acc[mt][2 * p],     ah[mt][0], ah[mt][1], ah[mt][2], ah[mt][3], bl0, bl1);
                    MMAF16(acc[mt][2 * p + 1], ah[mt][0], ah[mt][1], ah[mt][2], ah[mt][3], bl2, bl3);
                    MMAF16(acc[mt][2 * p],     al[mt][0], al[mt][1], al[mt][2], al[mt][3], bh0, bh1);
                    MMAF16(acc[mt][2 * p + 1], al[mt][0], al[mt][1], al[mt][2], al[mt][3], bh2, bh3);
                }
            }
        }
        __syncthreads();
    }

    float* outp = g_kv + (size_t)bh * HDq * HDq;
    #pragma unroll
    for (int mt = 0; mt < 2; ++mt) {
        const int d0 = warp_m * 32 + mt * 16 + (lane >> 2);
        const int d1 = d0 + 8;
        #pragma unroll
        for (int nt = 0; nt < 8; ++nt) {
            const int e = warp_n * 64 + nt * 8 + (lane & 3) * 2;
            atomicAdd(&outp[d0 * HDq + e],     acc[mt][nt][0]);
            atomicAdd(&outp[d0 * HDq + e + 1], acc[mt][nt][1]);
            atomicAdd(&outp[d1 * HDq + e],     acc[mt][nt][2]);
            atomicAdd(&outp[d1 * HDq + e + 1], acc[mt][nt][3]);
        }
    }
}

// ---------------------------------------------------------------------------
// Kernel 5: out[n][e] = sum_d q[n][d] kv[d][e].  HMMA, 3-term.
// ---------------------------------------------------------------------------
#define OUT_QT_B  (128 * 256)
#define OUT_SMEM  (4 * OUT_QT_B)   // 128KB: qh, ql, kvh, kvl

__global__ __launch_bounds__(256, 1) void mma_out_gemm(float* __restrict__ out) {
    extern __shared__ char smem[];
    const uint32_t su = smem_u32(smem);
    const int tid = threadIdx.x;
    const int lane = tid & 31;
    const int wid = tid >> 5;
    const int warp_m = wid & 3;
    const int warp_n = wid >> 2;
    const int n0 = blockIdx.x * 128;
    const int bh = blockIdx.y;
    const int b = bh >> 3, h = bh & 7;

    const char* gqh = (const char*)g_qh + ((size_t)(b * Nq + n0) * Dq + h * HDq) * 2;
    const char* gql = (const char*)g_ql + ((size_t)(b * Nq + n0) * Dq + h * HDq) * 2;

    #pragma unroll
    for (int i = 0; i < 8; ++i) {
        const int w = tid + i * 256;         // 0..2047 = 128 rows * 16 units
        const int r = w >> 4;
        const int u = w & 15;
        const uint32_t so = swz256(r, u);
        const size_t go = (size_t)r * 2048 + (size_t)u * 16;
        CP_ASYNC16(su + 0 * OUT_QT_B + so, gqh + go);
        CP_ASYNC16(su + 1 * OUT_QT_B + so, gql + go);
    }
    CP_COMMIT();

    // convert kv f32 -> fp16 hi/lo into swizzled smem
    {
        const float* kvp = g_kv + (size_t)bh * HDq * HDq;
        __half* s_kvh = (__half*)(smem + 2 * OUT_QT_B);
        __half* s_kvl = (__half*)(smem + 3 * OUT_QT_B);
        #pragma unroll
        for (int i = 0; i < 64; ++i) {
            const int idx = tid + i * 256;   // 0..16383
            const int d = idx >> 7, e = idx & 127;
            const float v = kvp[idx];
            __half hh, hl;
            hsplit(v, hh, hl);
            const uint32_t off = swz256(d, e >> 3) + (e & 7) * 2;
            *reinterpret_cast<__half*>((char*)s_kvh + off) = hh;
            *reinterpret_cast<__half*>((char*)s_kvl + off) = hl;
        }
    }
    CP_WAIT(0);
    __syncthreads();

    float acc[2][8][4];
    #pragma unroll
    for (int mt = 0; mt < 2; mt++)
        #pragma unroll
        for (int nt = 0; nt < 8; nt++)
            #pragma unroll
            for (int k = 0; k < 4; k++) acc[mt][nt][k] = 0.f;

    #pragma unroll
    for (int kk = 0; kk < 8; ++kk) {         // K = d = 128
        uint32_t ah[2][4], al[2][4];
        #pragma unroll
        for (int mt = 0; mt < 2; ++mt) {
            const int r = warp_m * 32 + mt * 16 + (lane & 15);
            const int u = kk * 2 + (lane >> 4);
            const uint32_t so = swz256(r, u);
            LDSM4(ah[mt][0], ah[mt][1], ah[mt][2], ah[mt][3], su + 0 * OUT_QT_B + so);
            LDSM4(al[mt][0], al[mt][1], al[mt][2], al[mt][3], su + 1 * OUT_QT_B + so);
        }
        #pragma unroll
        for (int p = 0; p < 4; ++p) {
            const int e0 = warp_n * 64 + p * 16;
            const int kr = kk * 16 + (lane & 7) + ((lane >> 3) & 1) * 8;   // d row
            const int eu = (e0 >> 3) + ((lane >> 4) & 1);
            const uint32_t so = swz256(kr, eu);
            uint32_t bh0, bh1, bh2, bh3, bl0, bl1, bl2, bl3;
            LDSM4T(bh0, bh1, bh2, bh3, su + 2 * OUT_QT_B + so);
            LDSM4T(bl0, bl1, bl2, bl3, su + 3 * OUT_QT_B + so);
            #pragma unroll
            for (int mt = 0; mt < 2; ++mt) {
                MMAF16(acc[mt][2 * p],     ah[mt][0], ah[mt][1], ah[mt][2], ah[mt][3], bh0, bh1);
                MMAF16(acc[mt][2 * p + 1], ah[mt][0], ah[mt][1], ah[mt][2], ah[mt][3], bh2, bh3);
                MMAF16(acc[mt][2 * p],     ah[mt][0], ah[mt][1], ah[mt][2], ah[mt][3], bl0, bl1);
                MMAF16(acc[mt][2 * p + 1], ah[mt][0], ah[mt][1], ah[mt][2], ah[mt][3], bl2, bl3);
                MMAF16(acc[mt][2 * p],     al[mt][0], al[mt][1], al[mt][2], al[mt][3], bh0, bh1);
                MMAF16(acc[mt][2 * p + 1], al[mt][0], al[mt][1], al[mt][2], al[mt][3], bh2, bh3);
            }
        }
    }

    #pragma unroll
    for (int mt = 0; mt < 2; ++mt) {
        const int r0 = n0 + warp_m * 32 + mt * 16 + (lane >> 2);
        const int r1 = r0 + 8;
        #pragma unroll
        for (int nt = 0; nt < 8; ++nt) {
            const int e = warp_n * 64 + nt * 8 + (lane & 3) * 2;
            float* o0 = out + (size_t)(b * Nq + r0) * Dq + h * HDq + e;
            float* o1 = out + (size_t)(b * Nq + r1) * Dq + h * HDq + e;
            *reinterpret_cast<float2*>(o0) = make_float2(acc[mt][nt][0], acc[mt][nt][1]);
            *reinterpret_cast<float2*>(o1) = make_float2(acc[mt][nt][2], acc[mt][nt][3]);
        }
    }
}

// ---------------------------------------------------------------------------
// Launch: inputs in metadata order: x, mask, w_qkv, gamma, beta.
// ---------------------------------------------------------------------------
extern "C" void kernel_launch(void* const* d_in, const int* in_sizes, int n_in,
                              void* d_out, int out_size) {
    const float* x     = (const float*)d_in[0];
    const void*  mask  = d_in[1];
    const float* w     = (const float*)d_in[2];
    const float* gamma = (const float*)d_in[3];
    const float* beta  = (const float*)d_in[4];
    float* out         = (float*)d_out;

    static int smem_set = 0;
    if (!smem_set) {
        cudaFuncSetAttribute(mma_qkv_gemm, cudaFuncAttributeMaxDynamicSharedMemorySize, QKV_SMEM);
        cudaFuncSetAttribute(mma_kv_gemm,  cudaFuncAttributeMaxDynamicSharedMemorySize, KV_SMEM);
        cudaFuncSetAttribute(mma_out_gemm, cudaFuncAttributeMaxDynamicSharedMemorySize, OUT_SMEM);
        smem_set = 1;
    }

    mask_detect<<<1, 256>>>((const int*)mask);
    mask_expand<<<(Bq * Nq + 255) / 256, 256>>>(mask);
    ln_split<<<Bq * Nq, 256>>>(x, gamma, beta);
    w_split<<<dim3(TDq / 32, Dq / 32), dim3(32, 8)>>>(w);
    mma_qkv_gemm<<<dim3(TDq / 128, (Bq * Nq) / 128), 256, QKV_SMEM>>>();
    zero_kv<<<(Bq * Hq * HDq * HDq + 255) / 256, 256>>>();
    mma_kv_gemm<<<dim3(Bq * Hq, KV_SPLIT), 256, KV_SMEM>>>();
    mma_out_gemm<<<dim3(Nq / 128, Bq * Hq), 256, OUT_SMEM>>>(out);
}

// round 10
// speedup vs baseline: 5.6846x; 1.0472x over previous
#include <cuda_runtime.h>
#include <cuda_fp16.h>
#include <math.h>
#include <stdint.h>

#define Bq 4
#define Nq 8192
#define Dq 1024
#define Hq 8
#define HDq 128
#define TDq 3072
#define KV_SPLIT 16

// ---------------------------------------------------------------------------
// Device scratch.  q, k single fp16 (quantization ~2^-12 each, budgeted);
// v kept hi/lo (exact) so kv inherits only k's quantization.
// ---------------------------------------------------------------------------
__device__ __align__(16) __half g_xh[(size_t)Bq * Nq * Dq];   // LN(x) fp16
__device__ __align__(16) __half g_wth[(size_t)TDq * Dq];      // W^T fp16 [3072,1024]
__device__ __align__(16) __half g_q[(size_t)Bq * Nq * Dq];    // sigmoid(q)
__device__ __align__(16) __half g_k[(size_t)Bq * Nq * Dq];    // tanh(k)*mask
__device__ __align__(16) __half g_vh[(size_t)Bq * Nq * Dq];   // v hi/lo
__device__ __align__(16) __half g_vl[(size_t)Bq * Nq * Dq];
__device__ __align__(16) float g_kv[(size_t)Bq * Hq * HDq * HDq];
__device__ float g_maskf[(size_t)Bq * Nq];
__device__ int   g_mask_is_i32;

// ---------------------------------------------------------------------------
// PTX helpers (sm_80-level; tcgen05 rejected by base compute_103, per R4).
// ---------------------------------------------------------------------------
__device__ __forceinline__ uint32_t smem_u32(const void* p) {
    uint32_t a;
    asm("{ .reg .u64 t; cvta.to.shared.u64 t, %1; cvt.u32.u64 %0, t; }" : "=r"(a) : "l"(p));
    return a;
}
#define CP_ASYNC16(saddr, gptr) \
    asm volatile("cp.async.cg.shared.global [%0], [%1], 16;" :: "r"(saddr), "l"(gptr))
#define CP_COMMIT() asm volatile("cp.async.commit_group;" ::: "memory")
#define CP_WAIT(n)  asm volatile("cp.async.wait_group %0;" :: "n"(n) : "memory")

#define LDSM4(R0, R1, R2, R3, addr) \
    asm volatile("ldmatrix.sync.aligned.m8n8.x4.shared.b16 {%0,%1,%2,%3}, [%4];" \
                 : "=r"(R0), "=r"(R1), "=r"(R2), "=r"(R3) : "r"(addr))
#define LDSM4T(R0, R1, R2, R3, addr) \
    asm volatile("ldmatrix.sync.aligned.m8n8.x4.trans.shared.b16 {%0,%1,%2,%3}, [%4];" \
                 : "=r"(R0), "=r"(R1), "=r"(R2), "=r"(R3) : "r"(addr))

#define MMAF16(d, a0, a1, a2, a3, b0, b1) \
    asm volatile("mma.sync.aligned.m16n8k16.row.col.f32.f16.f16.f32 " \
                 "{%0,%1,%2,%3}, {%4,%5,%6,%7}, {%8,%9}, {%0,%1,%2,%3};" \
                 : "+f"((d)[0]), "+f"((d)[1]), "+f"((d)[2]), "+f"((d)[3]) \
                 : "r"(a0), "r"(a1), "r"(a2), "r"(a3), "r"(b0), "r"(b1))

// swizzles: 128B rows (qkv gemm) and 256B rows (head-sliced fp16 tiles)
__device__ __forceinline__ uint32_t swz(int r, int u) {
    return (uint32_t)(r * 128 + ((u ^ (r & 7)) << 4));
}
__device__ __forceinline__ uint32_t swz256(int r, int u) {
    return (uint32_t)(r * 256 + ((u ^ ((r & 7) << 1)) << 4));
}

__device__ __forceinline__ void hsplit(float v, __half& h, __half& l) {
    h = __float2half_rn(v);
    l = __float2half_rn(v - __half2float(h));
}

// ---------------------------------------------------------------------------
// Kernel 0a/0b: mask dtype detect + canonicalize.
// ---------------------------------------------------------------------------
__global__ void mask_detect(const int* __restrict__ m) {
    __shared__ int bad[8];
    int mybad = 0;
    for (int i = threadIdx.x; i < 4096; i += blockDim.x) {
        const int v = m[i];
        if (v != 0 && v != 1) mybad = 1;
    }
    #pragma unroll
    for (int o = 16; o > 0; o >>= 1) mybad |= __shfl_down_sync(0xffffffffu, mybad, o);
    if ((threadIdx.x & 31) == 0) bad[threadIdx.x >> 5] = mybad;
    __syncthreads();
    if (threadIdx.x == 0) {
        int t = 0;
        #pragma unroll
        for (int i = 0; i < 8; i++) t |= bad[i];
        g_mask_is_i32 = t ? 0 : 1;
    }
}
__global__ void mask_expand(const void* __restrict__ m) {
    const int i = blockIdx.x * blockDim.x + threadIdx.x;
    if (i >= Bq * Nq) return;
    int set;
    if (g_mask_is_i32) set = ((const int*)m)[i] != 0;
    else               set = ((const unsigned char*)m)[i] != 0;
    g_maskf[i] = set ? 0.0f : 1.0f;
}

// ---------------------------------------------------------------------------
// Kernel 1: LayerNorm -> fp16.
// ---------------------------------------------------------------------------
__global__ void ln_split(const float* __restrict__ x,
                         const float* __restrict__ gamma,
                         const float* __restrict__ beta) {
    const int row = blockIdx.x;
    const int t = threadIdx.x;
    const float4 a = reinterpret_cast<const float4*>(x + (size_t)row * Dq)[t];
    float s  = a.x + a.y + a.z + a.w;
    float ss = a.x * a.x + a.y * a.y + a.z * a.z + a.w * a.w;

    __shared__ float red[16];
    __shared__ float mv[2];
    #pragma unroll
    for (int o = 16; o > 0; o >>= 1) {
        s  += __shfl_down_sync(0xffffffffu, s, o);
        ss += __shfl_down_sync(0xffffffffu, ss, o);
    }
    const int w = t >> 5, l = t & 31;
    if (l == 0) { red[w] = s; red[w + 8] = ss; }
    __syncthreads();
    if (t == 0) {
        float ts = 0.f, tss = 0.f;
        #pragma unroll
        for (int i = 0; i < 8; i++) { ts += red[i]; tss += red[i + 8]; }
        const float mean = ts * (1.0f / Dq);
        const float var  = tss * (1.0f / Dq) - mean * mean;
        mv[0] = mean;
        mv[1] = rsqrtf(var + 1e-5f);
    }
    __syncthreads();
    const float mean = mv[0], rstd = mv[1];
    const float4 g4 = reinterpret_cast<const float4*>(gamma)[t];
    const float4 b4 = reinterpret_cast<const float4*>(beta)[t];
    const float o0 = (a.x - mean) * rstd * g4.x + b4.x;
    const float o1 = (a.y - mean) * rstd * g4.y + b4.y;
    const float o2 = (a.z - mean) * rstd * g4.z + b4.z;
    const float o3 = (a.w - mean) * rstd * g4.w + b4.w;
    const size_t idx = (size_t)row * Dq + t * 4;
    *reinterpret_cast<__half2*>(g_xh + idx) =
        __halves2half2(__float2half_rn(o0), __float2half_rn(o1));
    *reinterpret_cast<__half2*>(g_xh + idx + 2) =
        __halves2half2(__float2half_rn(o2), __float2half_rn(o3));
}

// ---------------------------------------------------------------------------
// Kernel 2: W [1024,3072] fp32 -> W^T [3072,1024] fp16.
// ---------------------------------------------------------------------------
__global__ void w_split(const float* __restrict__ W) {
    __shared__ float tile[32][33];
    const int n0 = blockIdx.x * 32;
    const int k0 = blockIdx.y * 32;
    const int tx = threadIdx.x, ty = threadIdx.y;
    #pragma unroll
    for (int j = 0; j < 4; j++)
        tile[ty + 8 * j][tx] = W[(size_t)(k0 + ty + 8 * j) * TDq + n0 + tx];
    __syncthreads();
    #pragma unroll
    for (int j = 0; j < 4; j++) {
        const float v = tile[tx][ty + 8 * j];
        g_wth[(size_t)(n0 + ty + 8 * j) * Dq + k0 + tx] = __float2half_rn(v);
    }
}

// ---------------------------------------------------------------------------
// Kernel 3: HMMA QKV GEMM, single fp16 term, 6-stage cp.async pipeline.
// Epilogue: q, k -> single fp16; v -> fp16 hi/lo.
// ---------------------------------------------------------------------------
#define TILE_B   16384
#define STAGE_B  (2 * TILE_B)   // Ah, Bh
#define NSTAGE   6
#define QKV_SMEM (NSTAGE * STAGE_B)   // 192KB

__global__ __launch_bounds__(256, 1) void mma_qkv_gemm() {
    extern __shared__ char smem[];
    const uint32_t su = smem_u32(smem);
    const int tid = threadIdx.x;
    const int lane = tid & 31;
    const int wid = tid >> 5;
    const int warp_m = wid & 3;
    const int warp_n = wid >> 2;
    const int row0 = blockIdx.y * 128;
    const int col0 = blockIdx.x * 128;

    const char* gsrc0 = (const char*)g_xh  + (size_t)row0 * 2048;
    const char* gsrc2 = (const char*)g_wth + (size_t)col0 * 2048;

    auto load_stage = [&](int s, int c) {
        const uint32_t sb = su + s * STAGE_B;
        const size_t kb = (size_t)c * 128;
        #pragma unroll
        for (int i = 0; i < 4; ++i) {
            const int w = tid + i * 256;
            const int r = w >> 3;
            const int u = w & 7;
            const uint32_t so = swz(r, u);
            const size_t go = (size_t)r * 2048 + kb + (size_t)u * 16;
            CP_ASYNC16(sb + 0 * TILE_B + so, gsrc0 + go);
            CP_ASYNC16(sb + 1 * TILE_B + so, gsrc2 + go);
        }
    };

    float acc[2][8][4];
    #pragma unroll
    for (int mt = 0; mt < 2; mt++)
        #pragma unroll
        for (int nt = 0; nt < 8; nt++)
            #pragma unroll
            for (int k = 0; k < 4; k++) acc[mt][nt][k] = 0.f;

    load_stage(0, 0); CP_COMMIT();
    load_stage(1, 1); CP_COMMIT();
    load_stage(2, 2); CP_COMMIT();
    load_stage(3, 3); CP_COMMIT();
    load_stage(4, 4); CP_COMMIT();

    for (int c = 0; c < 16; ++c) {
        if (c + 5 < 16) {
            load_stage((c + 5) % NSTAGE, c + 5); CP_COMMIT();
            CP_WAIT(5);
        } else if (c + 4 < 16) {
            CP_WAIT(4);
        } else if (c + 3 < 16) {
            CP_WAIT(3);
        } else if (c + 2 < 16) {
            CP_WAIT(2);
        } else if (c + 1 < 16) {
            CP_WAIT(1);
        } else {
            CP_WAIT(0);
        }
        __syncthreads();

        const uint32_t sb = su + (c % NSTAGE) * STAGE_B;
        #pragma unroll
        for (int kk = 0; kk < 4; ++kk) {
            uint32_t ah[2][4];
            #pragma unroll
            for (int mt = 0; mt < 2; ++mt) {
                const int r = warp_m * 32 + mt * 16 + (lane & 15);
                const int u = kk * 2 + (lane >> 4);
                const uint32_t so = swz(r, u);
                LDSM4(ah[mt][0], ah[mt][1], ah[mt][2], ah[mt][3], sb + 0 * TILE_B + so);
            }
            #pragma unroll
            for (int p = 0; p < 4; ++p) {
                uint32_t bh0, bh1, bh2, bh3;
                const int rn = warp_n * 64 + p * 16 + (lane & 7) + ((lane >> 4) & 1) * 8;
                const int u = kk * 2 + ((lane >> 3) & 1);
                const uint32_t so = swz(rn, u);
                LDSM4(bh0, bh1, bh2, bh3, sb + 1 * TILE_B + so);
                #pragma unroll
                for (int mt = 0; mt < 2; ++mt) {
                    MMAF16(acc[mt][2 * p],     ah[mt][0], ah[mt][1], ah[mt][2], ah[mt][3], bh0, bh1);
                    MMAF16(acc[mt][2 * p + 1], ah[mt][0], ah[mt][1], ah[mt][2], ah[mt][3], bh2, bh3);
                }
            }
        }
        __syncthreads();
    }

    // epilogue: activation; q,k single fp16; v hi/lo.
    const int sec = blockIdx.x >> 3;     // 0=q, 1=k, 2=v
    const int csec0 = col0 - sec * Dq;   // column within the section [0,1024)
    #pragma unroll
    for (int mt = 0; mt < 2; ++mt) {
        const int r0 = row0 + warp_m * 32 + mt * 16 + (lane >> 2);
        const int r1 = r0 + 8;
        const float m0 = (sec == 1) ? g_maskf[r0] : 1.0f;
        const float m1 = (sec == 1) ? g_maskf[r1] : 1.0f;
        #pragma unroll
        for (int nt = 0; nt < 8; ++nt) {
            const int cc = csec0 + warp_n * 64 + nt * 8 + (lane & 3) * 2;
            float v0 = acc[mt][nt][0], v1 = acc[mt][nt][1];
            float v2 = acc[mt][nt][2], v3 = acc[mt][nt][3];
            if (sec == 0) {
                v0 = 1.0f / (1.0f + expf(-v0));
                v1 = 1.0f / (1.0f + expf(-v1));
                v2 = 1.0f / (1.0f + expf(-v2));
                v3 = 1.0f / (1.0f + expf(-v3));
                *reinterpret_cast<__half2*>(g_q + (size_t)r0 * Dq + cc) =
                    __halves2half2(__float2half_rn(v0), __float2half_rn(v1));
                *reinterpret_cast<__half2*>(g_q + (size_t)r1 * Dq + cc) =
                    __halves2half2(__float2half_rn(v2), __float2half_rn(v3));
            } else if (sec == 1) {
                v0 = tanhf(v0) * m0;
                v1 = tanhf(v1) * m0;
                v2 = tanhf(v2) * m1;
                v3 = tanhf(v3) * m1;
                *reinterpret_cast<__half2*>(g_k + (size_t)r0 * Dq + cc) =
                    __halves2half2(__float2half_rn(v0), __float2half_rn(v1));
                *reinterpret_cast<__half2*>(g_k + (size_t)r1 * Dq + cc) =
                    __halves2half2(__float2half_rn(v2), __float2half_rn(v3));
            } else {
                __half h0, h1, h2, h3, l0, l1, l2, l3;
                hsplit(v0, h0, l0); hsplit(v1, h1, l1);
                hsplit(v2, h2, l2); hsplit(v3, h3, l3);
                *reinterpret_cast<__half2*>(g_vh + (size_t)r0 * Dq + cc) = __halves2half2(h0, h1);
                *reinterpret_cast<__half2*>(g_vl + (size_t)r0 * Dq + cc) = __halves2half2(l0, l1);
                *reinterpret_cast<__half2*>(g_vh + (size_t)r1 * Dq + cc) = __halves2half2(h2, h3);
                *reinterpret_cast<__half2*>(g_vl + (size_t)r1 * Dq + cc) = __halves2half2(l2, l3);
            }
        }
    }
}

// ---------------------------------------------------------------------------
// Kernel 4a: zero kv accumulator.
// ---------------------------------------------------------------------------
__global__ void zero_kv() {
    const int i = blockIdx.x * blockDim.x + threadIdx.x;
    if (i < Bq * Hq * HDq * HDq) g_kv[i] = 0.f;
}

// ---------------------------------------------------------------------------
// Kernel 4b: kv[d][e] = sum_n k[n][d] v[n][e].  HMMA 2-term (k@vh + k@vl),
// trans loads, 3-stage ring with R8-validated prefetch-2 schedule.
// ---------------------------------------------------------------------------
#define KVT_B    8192           // 32 rows * 256B
#define KVSTG_B  (3 * KVT_B)    // k, vh, vl
#define KV_SMEM  (3 * KVSTG_B)  // 72KB

__global__ __launch_bounds__(256, 2) void mma_kv_gemm() {
    extern __shared__ char smem[];
    const uint32_t su = smem_u32(smem);
    const int tid = threadIdx.x;
    const int lane = tid & 31;
    const int wid = tid >> 5;
    const int warp_m = wid & 3;          // d tile: 32 rows
    const int warp_n = wid >> 2;         // e tile: 64 cols
    const int bh = blockIdx.x;           // 0..31
    const int split = blockIdx.y;        // 0..15
    const int b = bh >> 3, h = bh & 7;
    const int n0 = split * (Nq / KV_SPLIT);

    const char* gk  = (const char*)g_k  + ((size_t)(b * Nq + n0) * Dq + h * HDq) * 2;
    const char* gvh = (const char*)g_vh + ((size_t)(b * Nq + n0) * Dq + h * HDq) * 2;
    const char* gvl = (const char*)g_vl + ((size_t)(b * Nq + n0) * Dq + h * HDq) * 2;

    auto load_stage = [&](int s, int c) {
        const uint32_t sb = su + s * KVSTG_B;
        #pragma unroll
        for (int i = 0; i < 2; ++i) {
            const int w = tid + i * 256;     // 0..511 = 32 rows * 16 units
            const int r = w >> 4;
            const int u = w & 15;
            const uint32_t so = swz256(r, u);
            const size_t go = (size_t)(c * 32 + r) * 2048 + (size_t)u * 16;
            CP_ASYNC16(sb + 0 * KVT_B + so, gk  + go);
            CP_ASYNC16(sb + 1 * KVT_B + so, gvh + go);
            CP_ASYNC16(sb + 2 * KVT_B + so, gvl + go);
        }
    };

    float acc[2][8][4];
    #pragma unroll
    for (int mt = 0; mt < 2; mt++)
        #pragma unroll
        for (int nt = 0; nt < 8; nt++)
            #pragma unroll
            for (int k = 0; k < 4; k++) acc[mt][nt][k] = 0.f;

    load_stage(0, 0); CP_COMMIT();
    load_stage(1, 1); CP_COMMIT();

    const int NC = 16;                   // 512 n / 32
    for (int c = 0; c < NC; ++c) {
        if (c + 2 < NC) {
            load_stage((c + 2) % 3, c + 2); CP_COMMIT();
            CP_WAIT(2);
        } else if (c + 1 < NC) {
            CP_WAIT(1);
        } else {
            CP_WAIT(0);
        }
        __syncthreads();

        const uint32_t sb = su + (c % 3) * KVSTG_B;
        #pragma unroll
        for (int kk = 0; kk < 2; ++kk) {       // 2 x 16 n per stage
            uint32_t ah[2][4];
            #pragma unroll
            for (int mt = 0; mt < 2; ++mt) {
                const int m0 = warp_m * 32 + mt * 16;          // d
                const int kr = kk * 16 + (lane & 7) + ((lane >> 4) & 1) * 8;   // n row
                const int mu = (m0 >> 3) + ((lane >> 3) & 1);  // 16B unit along d
                const uint32_t so = swz256(kr, mu);
                LDSM4T(ah[mt][0], ah[mt][1], ah[mt][2], ah[mt][3], sb + 0 * KVT_B + so);
            }
            #pragma unroll
            for (int p = 0; p < 4; ++p) {
                const int e0 = warp_n * 64 + p * 16;
                const int kr = kk * 16 + (lane & 7) + ((lane >> 3) & 1) * 8;
                const int eu = (e0 >> 3) + ((lane >> 4) & 1);
                const uint32_t so = swz256(kr, eu);
                uint32_t bh0, bh1, bh2, bh3, bl0, bl1, bl2, bl3;
                LDSM4T(bh0, bh1, bh2, bh3, sb + 1 * KVT_B + so);
                LDSM4T(bl0, bl1, bl2, bl3, sb + 2 * KVT_B + so);
                #pragma unroll
                for (int mt = 0; mt < 2; ++mt) {
                    MMAF16(acc[mt][2 * p],     ah[mt][0], ah[mt][1], ah[mt][2], ah[mt][3], bh0, bh1);
                    MMAF16(acc[mt][2 * p + 1], ah[mt][0], ah[mt][1], ah[mt][2], ah[mt][3], bh2, bh3);
                    MMAF16(acc[mt][2 * p],     ah[mt][0], ah[mt][1], ah[mt][2], ah[mt][3], bl0, bl1);
                    MMAF16(acc[mt][2 * p + 1], ah[mt][0], ah[mt][1], ah[mt][2], ah[mt][3], bl2, bl3);
                }
            }
        }
        __syncthreads();
    }

    float* outp = g_kv + (size_t)bh * HDq * HDq;
    #pragma unroll
    for (int mt = 0; mt < 2; ++mt) {
        const int d0 = warp_m * 32 + mt * 16 + (lane >> 2);
        const int d1 = d0 + 8;
        #pragma unroll
        for (int nt = 0; nt < 8; ++nt) {
            const int e = warp_n * 64 + nt * 8 + (lane & 3) * 2;
            atomicAdd(&outp[d0 * HDq + e],     acc[mt][nt][0]);
            atomicAdd(&outp[d0 * HDq + e + 1], acc[mt][nt][1]);
            atomicAdd(&outp[d1 * HDq + e],     acc[mt][nt][2]);
            atomicAdd(&outp[d1 * HDq + e + 1], acc[mt][nt][3]);
        }
    }
}

// ---------------------------------------------------------------------------
// Kernel 5: out[n][e] = sum_d q[n][d] kv[d][e].  HMMA 2-term (q@kvh + q@kvl).
// ---------------------------------------------------------------------------
#define OUT_QT_B  (128 * 256)
#define OUT_SMEM  (3 * OUT_QT_B)   // 96KB: q, kvh, kvl

__global__ __launch_bounds__(256, 1) void mma_out_gemm(float* __restrict__ out) {
    extern __shared__ char smem[];
    const uint32_t su = smem_u32(smem);
    const int tid = threadIdx.x;
    const int lane = tid & 31;
    const int wid = tid >> 5;
    const int warp_m = wid & 3;
    const int warp_n = wid >> 2;
    const int n0 = blockIdx.x * 128;
    const int bh = blockIdx.y;
    const int b = bh >> 3, h = bh & 7;

    const char* gq = (const char*)g_q + ((size_t)(b * Nq + n0) * Dq + h * HDq) * 2;

    #pragma unroll
    for (int i = 0; i < 8; ++i) {
        const int w = tid + i * 256;         // 0..2047 = 128 rows * 16 units
        const int r = w >> 4;
        const int u = w & 15;
        const uint32_t so = swz256(r, u);
        const size_t go = (size_t)r * 2048 + (size_t)u * 16;
        CP_ASYNC16(su + 0 * OUT_QT_B + so, gq + go);
    }
    CP_COMMIT();

    // convert kv f32 -> fp16 hi/lo into swizzled smem
    {
        const float* kvp = g_kv + (size_t)bh * HDq * HDq;
        __half* s_kvh = (__half*)(smem + 1 * OUT_QT_B);
        __half* s_kvl = (__half*)(smem + 2 * OUT_QT_B);
        #pragma unroll
        for (int i = 0; i < 64; ++i) {
            const int idx = tid + i * 256;   // 0..16383
            const int d = idx >> 7, e = idx & 127;
            const float v = kvp[idx];
            __half hh, hl;
            hsplit(v, hh, hl);
            const uint32_t off = swz256(d, e >> 3) + (e & 7) * 2;
            *reinterpret_cast<__half*>((char*)s_kvh + off) = hh;
            *reinterpret_cast<__half*>((char*)s_kvl + off) = hl;
        }
    }
    CP_WAIT(0);
    __syncthreads();

    float acc[2][8][4];
    #pragma unroll
    for (int mt = 0; mt < 2; mt++)
        #pragma unroll
        for (int nt = 0; nt < 8; nt++)
            #pragma unroll
            for (int k = 0; k < 4; k++) acc[mt][nt][k] = 0.f;

    #pragma unroll
    for (int kk = 0; kk < 8; ++kk) {         // K = d = 128
        uint32_t ah[2][4];
        #pragma unroll
        for (int mt = 0; mt < 2; ++mt) {
            const int r = warp_m * 32 + mt * 16 + (lane & 15);
            const int u = kk * 2 + (lane >> 4);
            const uint32_t so = swz256(r, u);
            LDSM4(ah[mt][0], ah[mt][1], ah[mt][2], ah[mt][3], su + 0 * OUT_QT_B + so);
        }
        #pragma unroll
        for (int p = 0; p < 4; ++p) {
            const int e0 = warp_n * 64 + p * 16;
            const int kr = kk * 16 + (lane & 7) + ((lane >> 3) & 1) * 8;   // d row
            const int eu = (e0 >> 3) + ((lane >> 4) & 1);
            const uint32_t so = swz256(kr, eu);
            uint32_t bh0, bh1, bh2, bh3, bl0, bl1, bl2, bl3;
            LDSM4T(bh0, bh1, bh2, bh3, su + 1 * OUT_QT_B + so);
            LDSM4T(bl0, bl1, bl2, bl3, su + 2 * OUT_QT_B + so);
            #pragma unroll
            for (int mt = 0; mt < 2; ++mt) {
                MMAF16(acc[mt][2 * p],     ah[mt][0], ah[mt][1], ah[mt][2], ah[mt][3], bh0, bh1);
                MMAF16(acc[mt][2 * p + 1], ah[mt][0], ah[mt][1], ah[mt][2], ah[mt][3], bh2, bh3);
                MMAF16(acc[mt][2 * p],     ah[mt][0], ah[mt][1], ah[mt][2], ah[mt][3], bl0, bl1);
                MMAF16(acc[mt][2 * p + 1], ah[mt][0], ah[mt][1], ah[mt][2], ah[mt][3], bl2, bl3);
            }
        }
    }

    #pragma unroll
    for (int mt = 0; mt < 2; ++mt) {
        const int r0 = n0 + warp_m * 32 + mt * 16 + (lane >> 2);
        const int r1 = r0 + 8;
        #pragma unroll
        for (int nt = 0; nt < 8; ++nt) {
            const int e = warp_n * 64 + nt * 8 + (lane & 3) * 2;
            float* o0 = out + (size_t)(b * Nq + r0) * Dq + h * HDq + e;
            float* o1 = out + (size_t)(b * Nq + r1) * Dq + h * HDq + e;
            *reinterpret_cast<float2*>(o0) = make_float2(acc[mt][nt][0], acc[mt][nt][1]);
            *reinterpret_cast<float2*>(o1) = make_float2(acc[mt][nt][2], acc[mt][nt][3]);
        }
    }
}

// ---------------------------------------------------------------------------
// Launch: inputs in metadata order: x, mask, w_qkv, gamma, beta.
// ---------------------------------------------------------------------------
extern "C" void kernel_launch(void* const* d_in, const int* in_sizes, int n_in,
                              void* d_out, int out_size) {
    const float* x     = (const float*)d_in[0];
    const void*  mask  = d_in[1];
    const float* w     = (const float*)d_in[2];
    const float* gamma = (const float*)d_in[3];
    const float* beta  = (const float*)d_in[4];
    float* out         = (float*)d_out;

    static int smem_set = 0;
    if (!smem_set) {
        cudaFuncSetAttribute(mma_qkv_gemm, cudaFuncAttributeMaxDynamicSharedMemorySize, QKV_SMEM);
        cudaFuncSetAttribute(mma_kv_gemm,  cudaFuncAttributeMaxDynamicSharedMemorySize, KV_SMEM);
        cudaFuncSetAttribute(mma_out_gemm, cudaFuncAttributeMaxDynamicSharedMemorySize, OUT_SMEM);
        smem_set = 1;
    }

    mask_detect<<<1, 256>>>((const int*)mask);
    mask_expand<<<(Bq * Nq + 255) / 256, 256>>>(mask);
    ln_split<<<Bq * Nq, 256>>>(x, gamma, beta);
    w_split<<<dim3(TDq / 32, Dq / 32), dim3(32, 8)>>>(w);
    mma_qkv_gemm<<<dim3(TDq / 128, (Bq * Nq) / 128), 256, QKV_SMEM>>>();
    zero_kv<<<(Bq * Hq * HDq * HDq + 255) / 256, 256>>>();
    mma_kv_gemm<<<dim3(Bq * Hq, KV_SPLIT), 256, KV_SMEM>>>();
    mma_out_gemm<<<dim3(Nq / 128, Bq * Hq), 256, OUT_SMEM>>>(out);
}

// round 11
// speedup vs baseline: 6.3141x; 1.1107x over previous
#include <cuda_runtime.h>
#include <cuda_fp16.h>
#include <math.h>
#include <stdint.h>

#define Bq 4
#define Nq 8192
#define Dq 1024
#define Hq 8
#define HDq 128
#define TDq 3072
#define KV_SPLIT 16

// ---------------------------------------------------------------------------
// Device scratch.
// ---------------------------------------------------------------------------
__device__ __align__(16) __half g_xh[(size_t)Bq * Nq * Dq];   // LN(x) fp16
__device__ __align__(16) __half g_wth[(size_t)TDq * Dq];      // W^T fp16 [3072,1024]
__device__ __align__(16) __half g_q[(size_t)Bq * Nq * Dq];    // sigmoid(q)
__device__ __align__(16) __half g_k[(size_t)Bq * Nq * Dq];    // tanh(k)*mask
__device__ __align__(16) __half g_vh[(size_t)Bq * Nq * Dq];   // v hi/lo
__device__ __align__(16) __half g_vl[(size_t)Bq * Nq * Dq];
__device__ __align__(16) float g_kv[(size_t)Bq * Hq * HDq * HDq];
__device__ float g_maskf[(size_t)Bq * Nq];
__device__ int   g_mask_is_i32;

// ---------------------------------------------------------------------------
// PTX helpers (sm_80-level; tcgen05 rejected by base compute_103, per R4).
// ---------------------------------------------------------------------------
__device__ __forceinline__ uint32_t smem_u32(const void* p) {
    uint32_t a;
    asm("{ .reg .u64 t; cvta.to.shared.u64 t, %1; cvt.u32.u64 %0, t; }" : "=r"(a) : "l"(p));
    return a;
}
#define CP_ASYNC16(saddr, gptr) \
    asm volatile("cp.async.cg.shared.global [%0], [%1], 16;" :: "r"(saddr), "l"(gptr))
#define CP_COMMIT() asm volatile("cp.async.commit_group;" ::: "memory")
#define CP_WAIT(n)  asm volatile("cp.async.wait_group %0;" :: "n"(n) : "memory")

#define LDSM4(R0, R1, R2, R3, addr) \
    asm volatile("ldmatrix.sync.aligned.m8n8.x4.shared.b16 {%0,%1,%2,%3}, [%4];" \
                 : "=r"(R0), "=r"(R1), "=r"(R2), "=r"(R3) : "r"(addr))
#define LDSM4T(R0, R1, R2, R3, addr) \
    asm volatile("ldmatrix.sync.aligned.m8n8.x4.trans.shared.b16 {%0,%1,%2,%3}, [%4];" \
                 : "=r"(R0), "=r"(R1), "=r"(R2), "=r"(R3) : "r"(addr))

#define MMAF16(d, a0, a1, a2, a3, b0, b1) \
    asm volatile("mma.sync.aligned.m16n8k16.row.col.f32.f16.f16.f32 " \
                 "{%0,%1,%2,%3}, {%4,%5,%6,%7}, {%8,%9}, {%0,%1,%2,%3};" \
                 : "+f"((d)[0]), "+f"((d)[1]), "+f"((d)[2]), "+f"((d)[3]) \
                 : "r"(a0), "r"(a1), "r"(a2), "r"(a3), "r"(b0), "r"(b1))

// swizzles: 128B rows (qkv gemm) and 256B rows (head-sliced fp16 tiles)
__device__ __forceinline__ uint32_t swz(int r, int u) {
    return (uint32_t)(r * 128 + ((u ^ (r & 7)) << 4));
}
__device__ __forceinline__ uint32_t swz256(int r, int u) {
    return (uint32_t)(r * 256 + ((u ^ ((r & 7) << 1)) << 4));
}

__device__ __forceinline__ void hsplit(float v, __half& h, __half& l) {
    h = __float2half_rn(v);
    l = __float2half_rn(v - __half2float(h));
}

// ---------------------------------------------------------------------------
// Kernel 0a/0b: mask dtype detect + canonicalize.
// ---------------------------------------------------------------------------
__global__ void mask_detect(const int* __restrict__ m) {
    __shared__ int bad[8];
    int mybad = 0;
    for (int i = threadIdx.x; i < 4096; i += blockDim.x) {
        const int v = m[i];
        if (v != 0 && v != 1) mybad = 1;
    }
    #pragma unroll
    for (int o = 16; o > 0; o >>= 1) mybad |= __shfl_down_sync(0xffffffffu, mybad, o);
    if ((threadIdx.x & 31) == 0) bad[threadIdx.x >> 5] = mybad;
    __syncthreads();
    if (threadIdx.x == 0) {
        int t = 0;
        #pragma unroll
        for (int i = 0; i < 8; i++) t |= bad[i];
        g_mask_is_i32 = t ? 0 : 1;
    }
}
__global__ void mask_expand(const void* __restrict__ m) {
    const int i = blockIdx.x * blockDim.x + threadIdx.x;
    if (i >= Bq * Nq) return;
    int set;
    if (g_mask_is_i32) set = ((const int*)m)[i] != 0;
    else               set = ((const unsigned char*)m)[i] != 0;
    g_maskf[i] = set ? 0.0f : 1.0f;
}

// ---------------------------------------------------------------------------
// Kernel 1: LayerNorm -> fp16.
// ---------------------------------------------------------------------------
__global__ void ln_split(const float* __restrict__ x,
                         const float* __restrict__ gamma,
                         const float* __restrict__ beta) {
    const int row = blockIdx.x;
    const int t = threadIdx.x;
    const float4 a = reinterpret_cast<const float4*>(x + (size_t)row * Dq)[t];
    float s  = a.x + a.y + a.z + a.w;
    float ss = a.x * a.x + a.y * a.y + a.z * a.z + a.w * a.w;

    __shared__ float red[16];
    __shared__ float mv[2];
    #pragma unroll
    for (int o = 16; o > 0; o >>= 1) {
        s  += __shfl_down_sync(0xffffffffu, s, o);
        ss += __shfl_down_sync(0xffffffffu, ss, o);
    }
    const int w = t >> 5, l = t & 31;
    if (l == 0) { red[w] = s; red[w + 8] = ss; }
    __syncthreads();
    if (t == 0) {
        float ts = 0.f, tss = 0.f;
        #pragma unroll
        for (int i = 0; i < 8; i++) { ts += red[i]; tss += red[i + 8]; }
        const float mean = ts * (1.0f / Dq);
        const float var  = tss * (1.0f / Dq) - mean * mean;
        mv[0] = mean;
        mv[1] = rsqrtf(var + 1e-5f);
    }
    __syncthreads();
    const float mean = mv[0], rstd = mv[1];
    const float4 g4 = reinterpret_cast<const float4*>(gamma)[t];
    const float4 b4 = reinterpret_cast<const float4*>(beta)[t];
    const float o0 = (a.x - mean) * rstd * g4.x + b4.x;
    const float o1 = (a.y - mean) * rstd * g4.y + b4.y;
    const float o2 = (a.z - mean) * rstd * g4.z + b4.z;
    const float o3 = (a.w - mean) * rstd * g4.w + b4.w;
    const size_t idx = (size_t)row * Dq + t * 4;
    *reinterpret_cast<__half2*>(g_xh + idx) =
        __halves2half2(__float2half_rn(o0), __float2half_rn(o1));
    *reinterpret_cast<__half2*>(g_xh + idx + 2) =
        __halves2half2(__float2half_rn(o2), __float2half_rn(o3));
}

// ---------------------------------------------------------------------------
// Kernel 2: W [1024,3072] fp32 -> W^T [3072,1024] fp16.
// ---------------------------------------------------------------------------
__global__ void w_split(const float* __restrict__ W) {
    __shared__ float tile[32][33];
    const int n0 = blockIdx.x * 32;
    const int k0 = blockIdx.y * 32;
    const int tx = threadIdx.x, ty = threadIdx.y;
    #pragma unroll
    for (int j = 0; j < 4; j++)
        tile[ty + 8 * j][tx] = W[(size_t)(k0 + ty + 8 * j) * TDq + n0 + tx];
    __syncthreads();
    #pragma unroll
    for (int j = 0; j < 4; j++) {
        const float v = tile[tx][ty + 8 * j];
        g_wth[(size_t)(n0 + ty + 8 * j) * Dq + k0 + tx] = __float2half_rn(v);
    }
}

// ---------------------------------------------------------------------------
// Kernel 3: HMMA QKV GEMM, single fp16 term, 128x256 tile (smem-traffic
// optimized: 160B/MMA vs 384B/MMA at 128x128), 4-stage cp.async pipeline.
// 8 warps 4m x 2n; each warp: 2 m-tiles x 16 n8-tiles (128 acc regs).
// ---------------------------------------------------------------------------
#define AT_B     16384                 // A tile: 128 rows * 128B
#define BT_B     32768                 // B tile: 256 rows * 128B
#define STAGE_B  (AT_B + BT_B)         // 48KB
#define NSTAGE   4
#define QKV_SMEM (NSTAGE * STAGE_B)    // 192KB

__global__ __launch_bounds__(256, 1) void mma_qkv_gemm() {
    extern __shared__ char smem[];
    const uint32_t su = smem_u32(smem);
    const int tid = threadIdx.x;
    const int lane = tid & 31;
    const int wid = tid >> 5;
    const int warp_m = wid & 3;          // 32 rows each
    const int warp_n = wid >> 2;         // 128 cols each
    const int row0 = blockIdx.y * 128;
    const int col0 = blockIdx.x * 256;

    const char* gsrcA = (const char*)g_xh  + (size_t)row0 * 2048;
    const char* gsrcB = (const char*)g_wth + (size_t)col0 * 2048;

    auto load_stage = [&](int s, int c) {
        const uint32_t sb = su + s * STAGE_B;
        const size_t kb = (size_t)c * 128;
        #pragma unroll
        for (int i = 0; i < 4; ++i) {        // A: 1024 16B units
            const int w = tid + i * 256;
            const int r = w >> 3;
            const int u = w & 7;
            CP_ASYNC16(sb + swz(r, u), gsrcA + (size_t)r * 2048 + kb + (size_t)u * 16);
        }
        #pragma unroll
        for (int i = 0; i < 8; ++i) {        // B: 2048 16B units
            const int w = tid + i * 256;
            const int r = w >> 3;
            const int u = w & 7;
            CP_ASYNC16(sb + AT_B + swz(r, u), gsrcB + (size_t)r * 2048 + kb + (size_t)u * 16);
        }
    };

    float acc[2][16][4];
    #pragma unroll
    for (int mt = 0; mt < 2; mt++)
        #pragma unroll
        for (int nt = 0; nt < 16; nt++)
            #pragma unroll
            for (int k = 0; k < 4; k++) acc[mt][nt][k] = 0.f;

    load_stage(0, 0); CP_COMMIT();
    load_stage(1, 1); CP_COMMIT();
    load_stage(2, 2); CP_COMMIT();

    for (int c = 0; c < 16; ++c) {
        if (c + 3 < 16) {
            load_stage((c + 3) % NSTAGE, c + 3); CP_COMMIT();
            CP_WAIT(3);
        } else if (c + 2 < 16) {
            CP_WAIT(2);
        } else if (c + 1 < 16) {
            CP_WAIT(1);
        } else {
            CP_WAIT(0);
        }
        __syncthreads();

        const uint32_t sb = su + (c % NSTAGE) * STAGE_B;
        #pragma unroll
        for (int kk = 0; kk < 4; ++kk) {
            uint32_t ah[2][4];
            #pragma unroll
            for (int mt = 0; mt < 2; ++mt) {
                const int r = warp_m * 32 + mt * 16 + (lane & 15);
                const int u = kk * 2 + (lane >> 4);
                LDSM4(ah[mt][0], ah[mt][1], ah[mt][2], ah[mt][3], sb + swz(r, u));
            }
            #pragma unroll
            for (int p = 0; p < 8; ++p) {
                uint32_t bh0, bh1, bh2, bh3;
                const int rn = warp_n * 128 + p * 16 + (lane & 7) + ((lane >> 4) & 1) * 8;
                const int u = kk * 2 + ((lane >> 3) & 1);
                LDSM4(bh0, bh1, bh2, bh3, sb + AT_B + swz(rn, u));
                #pragma unroll
                for (int mt = 0; mt < 2; ++mt) {
                    MMAF16(acc[mt][2 * p],     ah[mt][0], ah[mt][1], ah[mt][2], ah[mt][3], bh0, bh1);
                    MMAF16(acc[mt][2 * p + 1], ah[mt][0], ah[mt][1], ah[mt][2], ah[mt][3], bh2, bh3);
                }
            }
        }
        __syncthreads();
    }

    // epilogue: activation; q,k single fp16; v hi/lo.
    const int sec = blockIdx.x >> 2;     // 4 x 256-wide blocks per section
    const int csec0 = col0 - sec * Dq;   // column within the section [0,1024)
    #pragma unroll
    for (int mt = 0; mt < 2; ++mt) {
        const int r0 = row0 + warp_m * 32 + mt * 16 + (lane >> 2);
        const int r1 = r0 + 8;
        const float m0 = (sec == 1) ? g_maskf[r0] : 1.0f;
        const float m1 = (sec == 1) ? g_maskf[r1] : 1.0f;
        #pragma unroll
        for (int nt = 0; nt < 16; ++nt) {
            const int cc = csec0 + warp_n * 128 + nt * 8 + (lane & 3) * 2;
            float v0 = acc[mt][nt][0], v1 = acc[mt][nt][1];
            float v2 = acc[mt][nt][2], v3 = acc[mt][nt][3];
            if (sec == 0) {
                v0 = 1.0f / (1.0f + expf(-v0));
                v1 = 1.0f / (1.0f + expf(-v1));
                v2 = 1.0f / (1.0f + expf(-v2));
                v3 = 1.0f / (1.0f + expf(-v3));
                *reinterpret_cast<__half2*>(g_q + (size_t)r0 * Dq + cc) =
                    __halves2half2(__float2half_rn(v0), __float2half_rn(v1));
                *reinterpret_cast<__half2*>(g_q + (size_t)r1 * Dq + cc) =
                    __halves2half2(__float2half_rn(v2), __float2half_rn(v3));
            } else if (sec == 1) {
                v0 = tanhf(v0) * m0;
                v1 = tanhf(v1) * m0;
                v2 = tanhf(v2) * m1;
                v3 = tanhf(v3) * m1;
                *reinterpret_cast<__half2*>(g_k + (size_t)r0 * Dq + cc) =
                    __halves2half2(__float2half_rn(v0), __float2half_rn(v1));
                *reinterpret_cast<__half2*>(g_k + (size_t)r1 * Dq + cc) =
                    __halves2half2(__float2half_rn(v2), __float2half_rn(v3));
            } else {
                __half h0, h1, h2, h3, l0, l1, l2, l3;
                hsplit(v0, h0, l0); hsplit(v1, h1, l1);
                hsplit(v2, h2, l2); hsplit(v3, h3, l3);
                *reinterpret_cast<__half2*>(g_vh + (size_t)r0 * Dq + cc) = __halves2half2(h0, h1);
                *reinterpret_cast<__half2*>(g_vl + (size_t)r0 * Dq + cc) = __halves2half2(l0, l1);
                *reinterpret_cast<__half2*>(g_vh + (size_t)r1 * Dq + cc) = __halves2half2(h2, h3);
                *reinterpret_cast<__half2*>(g_vl + (size_t)r1 * Dq + cc) = __halves2half2(l2, l3);
            }
        }
    }
}

// ---------------------------------------------------------------------------
// Kernel 4a: zero kv accumulator.
// ---------------------------------------------------------------------------
__global__ void zero_kv() {
    const int i = blockIdx.x * blockDim.x + threadIdx.x;
    if (i < Bq * Hq * HDq * HDq) g_kv[i] = 0.f;
}

// ---------------------------------------------------------------------------
// Kernel 4b: kv[d][e] = sum_n k[n][d] v[n][e].  HMMA 2-term (k@vh + k@vl),
// trans loads, 3-stage ring with R8-validated prefetch-2 schedule.
// ---------------------------------------------------------------------------
#define KVT_B    8192           // 32 rows * 256B
#define KVSTG_B  (3 * KVT_B)    // k, vh, vl
#define KV_SMEM  (3 * KVSTG_B)  // 72KB

__global__ __launch_bounds__(256, 2) void mma_kv_gemm() {
    extern __shared__ char smem[];
    const uint32_t su = smem_u32(smem);
    const int tid = threadIdx.x;
    const int lane = tid & 31;
    const int wid = tid >> 5;
    const int warp_m = wid & 3;          // d tile: 32 rows
    const int warp_n = wid >> 2;         // e tile: 64 cols
    const int bh = blockIdx.x;           // 0..31
    const int split = blockIdx.y;        // 0..15
    const int b = bh >> 3, h = bh & 7;
    const int n0 = split * (Nq / KV_SPLIT);

    const char* gk  = (const char*)g_k  + ((size_t)(b * Nq + n0) * Dq + h * HDq) * 2;
    const char* gvh = (const char*)g_vh + ((size_t)(b * Nq + n0) * Dq + h * HDq) * 2;
    const char* gvl = (const char*)g_vl + ((size_t)(b * Nq + n0) * Dq + h * HDq) * 2;

    auto load_stage = [&](int s, int c) {
        const uint32_t sb = su + s * KVSTG_B;
        #pragma unroll
        for (int i = 0; i < 2; ++i) {
            const int w = tid + i * 256;     // 0..511 = 32 rows * 16 units
            const int r = w >> 4;
            const int u = w & 15;
            const uint32_t so = swz256(r, u);
            const size_t go = (size_t)(c * 32 + r) * 2048 + (size_t)u * 16;
            CP_ASYNC16(sb + 0 * KVT_B + so, gk  + go);
            CP_ASYNC16(sb + 1 * KVT_B + so, gvh + go);
            CP_ASYNC16(sb + 2 * KVT_B + so, gvl + go);
        }
    };

    float acc[2][8][4];
    #pragma unroll
    for (int mt = 0; mt < 2; mt++)
        #pragma unroll
        for (int nt = 0; nt < 8; nt++)
            #pragma unroll
            for (int k = 0; k < 4; k++) acc[mt][nt][k] = 0.f;

    load_stage(0, 0); CP_COMMIT();
    load_stage(1, 1); CP_COMMIT();

    const int NC = 16;                   // 512 n / 32
    for (int c = 0; c < NC; ++c) {
        if (c + 2 < NC) {
            load_stage((c + 2) % 3, c + 2); CP_COMMIT();
            CP_WAIT(2);
        } else if (c + 1 < NC) {
            CP_WAIT(1);
        } else {
            CP_WAIT(0);
        }
        __syncthreads();

        const uint32_t sb = su + (c % 3) * KVSTG_B;
        #pragma unroll
        for (int kk = 0; kk < 2; ++kk) {       // 2 x 16 n per stage
            uint32_t ah[2][4];
            #pragma unroll
            for (int mt = 0; mt < 2; ++mt) {
                const int m0 = warp_m * 32 + mt * 16;          // d
                const int kr = kk * 16 + (lane & 7) + ((lane >> 4) & 1) * 8;   // n row
                const int mu = (m0 >> 3) + ((lane >> 3) & 1);  // 16B unit along d
                const uint32_t so = swz256(kr, mu);
                LDSM4T(ah[mt][0], ah[mt][1], ah[mt][2], ah[mt][3], sb + 0 * KVT_B + so);
            }
            #pragma unroll
            for (int p = 0; p < 4; ++p) {
                const int e0 = warp_n * 64 + p * 16;
                const int kr = kk * 16 + (lane & 7) + ((lane >> 3) & 1) * 8;
                const int eu = (e0 >> 3) + ((lane >> 4) & 1);
                const uint32_t so = swz256(kr, eu);
                uint32_t bh0, bh1, bh2, bh3, bl0, bl1, bl2, bl3;
                LDSM4T(bh0, bh1, bh2, bh3, sb + 1 * KVT_B + so);
                LDSM4T(bl0, bl1, bl2, bl3, sb + 2 * KVT_B + so);
                #pragma unroll
                for (int mt = 0; mt < 2; ++mt) {
                    MMAF16(acc[mt][2 * p],     ah[mt][0], ah[mt][1], ah[mt][2], ah[mt][3], bh0, bh1);
                    MMAF16(acc[mt][2 * p + 1], ah[mt][0], ah[mt][1], ah[mt][2], ah[mt][3], bh2, bh3);
                    MMAF16(acc[mt][2 * p],     ah[mt][0], ah[mt][1], ah[mt][2], ah[mt][3], bl0, bl1);
                    MMAF16(acc[mt][2 * p + 1], ah[mt][0], ah[mt][1], ah[mt][2], ah[mt][3], bl2, bl3);
                }
            }
        }
        __syncthreads();
    }

    float* outp = g_kv + (size_t)bh * HDq * HDq;
    #pragma unroll
    for (int mt = 0; mt < 2; ++mt) {
        const int d0 = warp_m * 32 + mt * 16 + (lane >> 2);
        const int d1 = d0 + 8;
        #pragma unroll
        for (int nt = 0; nt < 8; ++nt) {
            const int e = warp_n * 64 + nt * 8 + (lane & 3) * 2;
            atomicAdd(&outp[d0 * HDq + e],     acc[mt][nt][0]);
            atomicAdd(&outp[d0 * HDq + e + 1], acc[mt][nt][1]);
            atomicAdd(&outp[d1 * HDq + e],     acc[mt][nt][2]);
            atomicAdd(&outp[d1 * HDq + e + 1], acc[mt][nt][3]);
        }
    }
}

// ---------------------------------------------------------------------------
// Kernel 5: out[n][e] = sum_d q[n][d] kv[d][e].  HMMA 2-term (q@kvh + q@kvl).
// ---------------------------------------------------------------------------
#define OUT_QT_B  (128 * 256)
#define OUT_SMEM  (3 * OUT_QT_B)   // 96KB: q, kvh, kvl

__global__ __launch_bounds__(256, 1) void mma_out_gemm(float* __restrict__ out) {
    extern __shared__ char smem[];
    const uint32_t su = smem_u32(smem);
    const int tid = threadIdx.x;
    const int lane = tid & 31;
    const int wid = tid >> 5;
    const int warp_m = wid & 3;
    const int warp_n = wid >> 2;
    const int n0 = blockIdx.x * 128;
    const int bh = blockIdx.y;
    const int b = bh >> 3, h = bh & 7;

    const char* gq = (const char*)g_q + ((size_t)(b * Nq + n0) * Dq + h * HDq) * 2;

    #pragma unroll
    for (int i = 0; i < 8; ++i) {
        const int w = tid + i * 256;         // 0..2047 = 128 rows * 16 units
        const int r = w >> 4;
        const int u = w & 15;
        const uint32_t so = swz256(r, u);
        const size_t go = (size_t)r * 2048 + (size_t)u * 16;
        CP_ASYNC16(su + 0 * OUT_QT_B + so, gq + go);
    }
    CP_COMMIT();

    // convert kv f32 -> fp16 hi/lo into swizzled smem
    {
        const float* kvp = g_kv + (size_t)bh * HDq * HDq;
        __half* s_kvh = (__half*)(smem + 1 * OUT_QT_B);
        __half* s_kvl = (__half*)(smem + 2 * OUT_QT_B);
        #pragma unroll
        for (int i = 0; i < 64; ++i) {
            const int idx = tid + i * 256;   // 0..16383
            const int d = idx >> 7, e = idx & 127;
            const float v = kvp[idx];
            __half hh, hl;
            hsplit(v, hh, hl);
            const uint32_t off = swz256(d, e >> 3) + (e & 7) * 2;
            *reinterpret_cast<__half*>((char*)s_kvh + off) = hh;
            *reinterpret_cast<__half*>((char*)s_kvl + off) = hl;
        }
    }
    CP_WAIT(0);
    __syncthreads();

    float acc[2][8][4];
    #pragma unroll
    for (int mt = 0; mt < 2; mt++)
        #pragma unroll
        for (int nt = 0; nt < 8; nt++)
            #pragma unroll
            for (int k = 0; k < 4; k++) acc[mt][nt][k] = 0.f;

    #pragma unroll
    for (int kk = 0; kk < 8; ++kk) {         // K = d = 128
        uint32_t ah[2][4];
        #pragma unroll
        for (int mt = 0; mt < 2; ++mt) {
            const int r = warp_m * 32 + mt * 16 + (lane & 15);
            const int u = kk * 2 + (lane >> 4);
            const uint32_t so = swz256(r, u);
            LDSM4(ah[mt][0], ah[mt][1], ah[mt][2], ah[mt][3], su + 0 * OUT_QT_B + so);
        }
        #pragma unroll
        for (int p = 0; p < 4; ++p) {
            const int e0 = warp_n * 64 + p * 16;
            const int kr = kk * 16 + (lane & 7) + ((lane >> 3) & 1) * 8;   // d row
            const int eu = (e0 >> 3) + ((lane >> 4) & 1);
            const uint32_t so = swz256(kr, eu);
            uint32_t bh0, bh1, bh2, bh3, bl0, bl1, bl2, bl3;
            LDSM4T(bh0, bh1, bh2, bh3, su + 1 * OUT_QT_B + so);
            LDSM4T(bl0, bl1, bl2, bl3, su + 2 * OUT_QT_B + so);
            #pragma unroll
            for (int mt = 0; mt < 2; ++mt) {
                MMAF16(acc[mt][2 * p],     ah[mt][0], ah[mt][1], ah[mt][2], ah[mt][3], bh0, bh1);
                MMAF16(acc[mt][2 * p + 1], ah[mt][0], ah[mt][1], ah[mt][2], ah[mt][3], bh2, bh3);
                MMAF16(acc[mt][2 * p],     ah[mt][0], ah[mt][1], ah[mt][2], ah[mt][3], bl0, bl1);
                MMAF16(acc[mt][2 * p + 1], ah[mt][0], ah[mt][1], ah[mt][2], ah[mt][3], bl2, bl3);
            }
        }
    }

    #pragma unroll
    for (int mt = 0; mt < 2; ++mt) {
        const int r0 = n0 + warp_m * 32 + mt * 16 + (lane >> 2);
        const int r1 = r0 + 8;
        #pragma unroll
        for (int nt = 0; nt < 8; ++nt) {
            const int e = warp_n * 64 + nt * 8 + (lane & 3) * 2;
            float* o0 = out + (size_t)(b * Nq + r0) * Dq + h * HDq + e;
            float* o1 = out + (size_t)(b * Nq + r1) * Dq + h * HDq + e;
            *reinterpret_cast<float2*>(o0) = make_float2(acc[mt][nt][0], acc[mt][nt][1]);
            *reinterpret_cast<float2*>(o1) = make_float2(acc[mt][nt][2], acc[mt][nt][3]);
        }
    }
}

// ---------------------------------------------------------------------------
// Launch: inputs in metadata order: x, mask, w_qkv, gamma, beta.
// ---------------------------------------------------------------------------
extern "C" void kernel_launch(void* const* d_in, const int* in_sizes, int n_in,
                              void* d_out, int out_size) {
    const float* x     = (const float*)d_in[0];
    const void*  mask  = d_in[1];
    const float* w     = (const float*)d_in[2];
    const float* gamma = (const float*)d_in[3];
    const float* beta  = (const float*)d_in[4];
    float* out         = (float*)d_out;

    static int smem_set = 0;
    if (!smem_set) {
        cudaFuncSetAttribute(mma_qkv_gemm, cudaFuncAttributeMaxDynamicSharedMemorySize, QKV_SMEM);
        cudaFuncSetAttribute(mma_kv_gemm,  cudaFuncAttributeMaxDynamicSharedMemorySize, KV_SMEM);
        cudaFuncSetAttribute(mma_out_gemm, cudaFuncAttributeMaxDynamicSharedMemorySize, OUT_SMEM);
        smem_set = 1;
    }

    mask_detect<<<1, 256>>>((const int*)mask);
    mask_expand<<<(Bq * Nq + 255) / 256, 256>>>(mask);
    ln_split<<<Bq * Nq, 256>>>(x, gamma, beta);
    w_split<<<dim3(TDq / 32, Dq / 32), dim3(32, 8)>>>(w);
    mma_qkv_gemm<<<dim3(TDq / 256, (Bq * Nq) / 128), 256, QKV_SMEM>>>();
    zero_kv<<<(Bq * Hq * HDq * HDq + 255) / 256, 256>>>();
    mma_kv_gemm<<<dim3(Bq * Hq, KV_SPLIT), 256, KV_SMEM>>>();
    mma_out_gemm<<<dim3(Nq / 128, Bq * Hq), 256, OUT_SMEM>>>(out);
}

// round 12
// speedup vs baseline: 6.7968x; 1.0764x over previous
#include <cuda_runtime.h>
#include <cuda_fp16.h>
#include <math.h>
#include <stdint.h>

#define Bq 4
#define Nq 8192
#define Dq 1024
#define Hq 8
#define HDq 128
#define TDq 3072
#define KV_SPLIT 16

// ---------------------------------------------------------------------------
// Device scratch.  q, k, v single fp16 (each quantization ~2^-12, budgeted);
// kv accumulated in f32, consumed as hi/lo (exact).
// ---------------------------------------------------------------------------
__device__ __align__(16) __half g_xh[(size_t)Bq * Nq * Dq];   // LN(x) fp16
__device__ __align__(16) __half g_wth[(size_t)TDq * Dq];      // W^T fp16 [3072,1024]
__device__ __align__(16) __half g_q[(size_t)Bq * Nq * Dq];    // sigmoid(q)
__device__ __align__(16) __half g_k[(size_t)Bq * Nq * Dq];    // tanh(k)*mask
__device__ __align__(16) __half g_v[(size_t)Bq * Nq * Dq];    // v
__device__ __align__(16) float g_kv[(size_t)Bq * Hq * HDq * HDq];
__device__ float g_maskf[(size_t)Bq * Nq];
__device__ int   g_mask_is_i32;

// ---------------------------------------------------------------------------
// PTX helpers (sm_80-level; tcgen05 rejected by base compute_103, per R4).
// ---------------------------------------------------------------------------
__device__ __forceinline__ uint32_t smem_u32(const void* p) {
    uint32_t a;
    asm("{ .reg .u64 t; cvta.to.shared.u64 t, %1; cvt.u32.u64 %0, t; }" : "=r"(a) : "l"(p));
    return a;
}
#define CP_ASYNC16(saddr, gptr) \
    asm volatile("cp.async.cg.shared.global [%0], [%1], 16;" :: "r"(saddr), "l"(gptr))
#define CP_COMMIT() asm volatile("cp.async.commit_group;" ::: "memory")
#define CP_WAIT(n)  asm volatile("cp.async.wait_group %0;" :: "n"(n) : "memory")

#define LDSM4(R0, R1, R2, R3, addr) \
    asm volatile("ldmatrix.sync.aligned.m8n8.x4.shared.b16 {%0,%1,%2,%3}, [%4];" \
                 : "=r"(R0), "=r"(R1), "=r"(R2), "=r"(R3) : "r"(addr))
#define LDSM4T(R0, R1, R2, R3, addr) \
    asm volatile("ldmatrix.sync.aligned.m8n8.x4.trans.shared.b16 {%0,%1,%2,%3}, [%4];" \
                 : "=r"(R0), "=r"(R1), "=r"(R2), "=r"(R3) : "r"(addr))

#define MMAF16(d, a0, a1, a2, a3, b0, b1) \
    asm volatile("mma.sync.aligned.m16n8k16.row.col.f32.f16.f16.f32 " \
                 "{%0,%1,%2,%3}, {%4,%5,%6,%7}, {%8,%9}, {%0,%1,%2,%3};" \
                 : "+f"((d)[0]), "+f"((d)[1]), "+f"((d)[2]), "+f"((d)[3]) \
                 : "r"(a0), "r"(a1), "r"(a2), "r"(a3), "r"(b0), "r"(b1))

// swizzles: 128B rows (qkv gemm) and 256B rows (head-sliced fp16 tiles)
__device__ __forceinline__ uint32_t swz(int r, int u) {
    return (uint32_t)(r * 128 + ((u ^ (r & 7)) << 4));
}
__device__ __forceinline__ uint32_t swz256(int r, int u) {
    return (uint32_t)(r * 256 + ((u ^ ((r & 7) << 1)) << 4));
}

__device__ __forceinline__ void hsplit(float v, __half& h, __half& l) {
    h = __float2half_rn(v);
    l = __float2half_rn(v - __half2float(h));
}

// ---------------------------------------------------------------------------
// Kernel 0a/0b: mask dtype detect + canonicalize.
// ---------------------------------------------------------------------------
__global__ void mask_detect(const int* __restrict__ m) {
    __shared__ int bad[8];
    int mybad = 0;
    for (int i = threadIdx.x; i < 4096; i += blockDim.x) {
        const int v = m[i];
        if (v != 0 && v != 1) mybad = 1;
    }
    #pragma unroll
    for (int o = 16; o > 0; o >>= 1) mybad |= __shfl_down_sync(0xffffffffu, mybad, o);
    if ((threadIdx.x & 31) == 0) bad[threadIdx.x >> 5] = mybad;
    __syncthreads();
    if (threadIdx.x == 0) {
        int t = 0;
        #pragma unroll
        for (int i = 0; i < 8; i++) t |= bad[i];
        g_mask_is_i32 = t ? 0 : 1;
    }
}
__global__ void mask_expand(const void* __restrict__ m) {
    const int i = blockIdx.x * blockDim.x + threadIdx.x;
    if (i >= Bq * Nq) return;
    int set;
    if (g_mask_is_i32) set = ((const int*)m)[i] != 0;
    else               set = ((const unsigned char*)m)[i] != 0;
    g_maskf[i] = set ? 0.0f : 1.0f;
}

// ---------------------------------------------------------------------------
// Kernel 1: LayerNorm -> fp16.
// ---------------------------------------------------------------------------
__global__ void ln_split(const float* __restrict__ x,
                         const float* __restrict__ gamma,
                         const float* __restrict__ beta) {
    const int row = blockIdx.x;
    const int t = threadIdx.x;
    const float4 a = reinterpret_cast<const float4*>(x + (size_t)row * Dq)[t];
    float s  = a.x + a.y + a.z + a.w;
    float ss = a.x * a.x + a.y * a.y + a.z * a.z + a.w * a.w;

    __shared__ float red[16];
    __shared__ float mv[2];
    #pragma unroll
    for (int o = 16; o > 0; o >>= 1) {
        s  += __shfl_down_sync(0xffffffffu, s, o);
        ss += __shfl_down_sync(0xffffffffu, ss, o);
    }
    const int w = t >> 5, l = t & 31;
    if (l == 0) { red[w] = s; red[w + 8] = ss; }
    __syncthreads();
    if (t == 0) {
        float ts = 0.f, tss = 0.f;
        #pragma unroll
        for (int i = 0; i < 8; i++) { ts += red[i]; tss += red[i + 8]; }
        const float mean = ts * (1.0f / Dq);
        const float var  = tss * (1.0f / Dq) - mean * mean;
        mv[0] = mean;
        mv[1] = rsqrtf(var + 1e-5f);
    }
    __syncthreads();
    const float mean = mv[0], rstd = mv[1];
    const float4 g4 = reinterpret_cast<const float4*>(gamma)[t];
    const float4 b4 = reinterpret_cast<const float4*>(beta)[t];
    const float o0 = (a.x - mean) * rstd * g4.x + b4.x;
    const float o1 = (a.y - mean) * rstd * g4.y + b4.y;
    const float o2 = (a.z - mean) * rstd * g4.z + b4.z;
    const float o3 = (a.w - mean) * rstd * g4.w + b4.w;
    const size_t idx = (size_t)row * Dq + t * 4;
    *reinterpret_cast<__half2*>(g_xh + idx) =
        __halves2half2(__float2half_rn(o0), __float2half_rn(o1));
    *reinterpret_cast<__half2*>(g_xh + idx + 2) =
        __halves2half2(__float2half_rn(o2), __float2half_rn(o3));
}

// ---------------------------------------------------------------------------
// Kernel 2: W [1024,3072] fp32 -> W^T [3072,1024] fp16.
// ---------------------------------------------------------------------------
__global__ void w_split(const float* __restrict__ W) {
    __shared__ float tile[32][33];
    const int n0 = blockIdx.x * 32;
    const int k0 = blockIdx.y * 32;
    const int tx = threadIdx.x, ty = threadIdx.y;
    #pragma unroll
    for (int j = 0; j < 4; j++)
        tile[ty + 8 * j][tx] = W[(size_t)(k0 + ty + 8 * j) * TDq + n0 + tx];
    __syncthreads();
    #pragma unroll
    for (int j = 0; j < 4; j++) {
        const float v = tile[tx][ty + 8 * j];
        g_wth[(size_t)(n0 + ty + 8 * j) * Dq + k0 + tx] = __float2half_rn(v);
    }
}

// ---------------------------------------------------------------------------
// Kernel 3: HMMA QKV GEMM, single fp16 term, 128x256 tile, 4-stage pipeline.
// Epilogue: q, k, v -> single fp16.
// ---------------------------------------------------------------------------
#define AT_B     16384                 // A tile: 128 rows * 128B
#define BT_B     32768                 // B tile: 256 rows * 128B
#define STAGE_B  (AT_B + BT_B)         // 48KB
#define NSTAGE   4
#define QKV_SMEM (NSTAGE * STAGE_B)    // 192KB

__global__ __launch_bounds__(256, 1) void mma_qkv_gemm() {
    extern __shared__ char smem[];
    const uint32_t su = smem_u32(smem);
    const int tid = threadIdx.x;
    const int lane = tid & 31;
    const int wid = tid >> 5;
    const int warp_m = wid & 3;          // 32 rows each
    const int warp_n = wid >> 2;         // 128 cols each
    const int row0 = blockIdx.y * 128;
    const int col0 = blockIdx.x * 256;

    const char* gsrcA = (const char*)g_xh  + (size_t)row0 * 2048;
    const char* gsrcB = (const char*)g_wth + (size_t)col0 * 2048;

    auto load_stage = [&](int s, int c) {
        const uint32_t sb = su + s * STAGE_B;
        const size_t kb = (size_t)c * 128;
        #pragma unroll
        for (int i = 0; i < 4; ++i) {        // A: 1024 16B units
            const int w = tid + i * 256;
            const int r = w >> 3;
            const int u = w & 7;
            CP_ASYNC16(sb + swz(r, u), gsrcA + (size_t)r * 2048 + kb + (size_t)u * 16);
        }
        #pragma unroll
        for (int i = 0; i < 8; ++i) {        // B: 2048 16B units
            const int w = tid + i * 256;
            const int r = w >> 3;
            const int u = w & 7;
            CP_ASYNC16(sb + AT_B + swz(r, u), gsrcB + (size_t)r * 2048 + kb + (size_t)u * 16);
        }
    };

    float acc[2][16][4];
    #pragma unroll
    for (int mt = 0; mt < 2; mt++)
        #pragma unroll
        for (int nt = 0; nt < 16; nt++)
            #pragma unroll
            for (int k = 0; k < 4; k++) acc[mt][nt][k] = 0.f;

    load_stage(0, 0); CP_COMMIT();
    load_stage(1, 1); CP_COMMIT();
    load_stage(2, 2); CP_COMMIT();

    for (int c = 0; c < 16; ++c) {
        if (c + 3 < 16) {
            load_stage((c + 3) % NSTAGE, c + 3); CP_COMMIT();
            CP_WAIT(3);
        } else if (c + 2 < 16) {
            CP_WAIT(2);
        } else if (c + 1 < 16) {
            CP_WAIT(1);
        } else {
            CP_WAIT(0);
        }
        __syncthreads();

        const uint32_t sb = su + (c % NSTAGE) * STAGE_B;
        #pragma unroll
        for (int kk = 0; kk < 4; ++kk) {
            uint32_t ah[2][4];
            #pragma unroll
            for (int mt = 0; mt < 2; ++mt) {
                const int r = warp_m * 32 + mt * 16 + (lane & 15);
                const int u = kk * 2 + (lane >> 4);
                LDSM4(ah[mt][0], ah[mt][1], ah[mt][2], ah[mt][3], sb + swz(r, u));
            }
            #pragma unroll
            for (int p = 0; p < 8; ++p) {
                uint32_t bh0, bh1, bh2, bh3;
                const int rn = warp_n * 128 + p * 16 + (lane & 7) + ((lane >> 4) & 1) * 8;
                const int u = kk * 2 + ((lane >> 3) & 1);
                LDSM4(bh0, bh1, bh2, bh3, sb + AT_B + swz(rn, u));
                #pragma unroll
                for (int mt = 0; mt < 2; ++mt) {
                    MMAF16(acc[mt][2 * p],     ah[mt][0], ah[mt][1], ah[mt][2], ah[mt][3], bh0, bh1);
                    MMAF16(acc[mt][2 * p + 1], ah[mt][0], ah[mt][1], ah[mt][2], ah[mt][3], bh2, bh3);
                }
            }
        }
        __syncthreads();
    }

    // epilogue: activation; q, k, v all single fp16.
    const int sec = blockIdx.x >> 2;     // 4 x 256-wide blocks per section
    __half* dst = (sec == 0) ? g_q : (sec == 1) ? g_k : g_v;
    const int csec0 = col0 - sec * Dq;   // column within the section [0,1024)
    #pragma unroll
    for (int mt = 0; mt < 2; ++mt) {
        const int r0 = row0 + warp_m * 32 + mt * 16 + (lane >> 2);
        const int r1 = r0 + 8;
        const float m0 = (sec == 1) ? g_maskf[r0] : 1.0f;
        const float m1 = (sec == 1) ? g_maskf[r1] : 1.0f;
        #pragma unroll
        for (int nt = 0; nt < 16; ++nt) {
            const int cc = csec0 + warp_n * 128 + nt * 8 + (lane & 3) * 2;
            float v0 = acc[mt][nt][0], v1 = acc[mt][nt][1];
            float v2 = acc[mt][nt][2], v3 = acc[mt][nt][3];
            if (sec == 0) {
                v0 = 1.0f / (1.0f + expf(-v0));
                v1 = 1.0f / (1.0f + expf(-v1));
                v2 = 1.0f / (1.0f + expf(-v2));
                v3 = 1.0f / (1.0f + expf(-v3));
            } else if (sec == 1) {
                v0 = tanhf(v0) * m0;
                v1 = tanhf(v1) * m0;
                v2 = tanhf(v2) * m1;
                v3 = tanhf(v3) * m1;
            }
            *reinterpret_cast<__half2*>(dst + (size_t)r0 * Dq + cc) =
                __halves2half2(__float2half_rn(v0), __float2half_rn(v1));
            *reinterpret_cast<__half2*>(dst + (size_t)r1 * Dq + cc) =
                __halves2half2(__float2half_rn(v2), __float2half_rn(v3));
        }
    }
}

// ---------------------------------------------------------------------------
// Kernel 4a: zero kv accumulator.
// ---------------------------------------------------------------------------
__global__ void zero_kv() {
    const int i = blockIdx.x * blockDim.x + threadIdx.x;
    if (i < Bq * Hq * HDq * HDq) g_kv[i] = 0.f;
}

// ---------------------------------------------------------------------------
// Kernel 4b: kv[d][e] = sum_n k[n][d] v[n][e].  HMMA 1-term k@v,
// trans loads, 3-stage ring with R8-validated prefetch-2 schedule.
// ---------------------------------------------------------------------------
#define KVT_B    8192           // 32 rows * 256B
#define KVSTG_B  (2 * KVT_B)    // k, v
#define KV_SMEM  (3 * KVSTG_B)  // 48KB

__global__ __launch_bounds__(256, 2) void mma_kv_gemm() {
    extern __shared__ char smem[];
    const uint32_t su = smem_u32(smem);
    const int tid = threadIdx.x;
    const int lane = tid & 31;
    const int wid = tid >> 5;
    const int warp_m = wid & 3;          // d tile: 32 rows
    const int warp_n = wid >> 2;         // e tile: 64 cols
    const int bh = blockIdx.x;           // 0..31
    const int split = blockIdx.y;        // 0..15
    const int b = bh >> 3, h = bh & 7;
    const int n0 = split * (Nq / KV_SPLIT);

    const char* gk = (const char*)g_k + ((size_t)(b * Nq + n0) * Dq + h * HDq) * 2;
    const char* gv = (const char*)g_v + ((size_t)(b * Nq + n0) * Dq + h * HDq) * 2;

    auto load_stage = [&](int s, int c) {
        const uint32_t sb = su + s * KVSTG_B;
        #pragma unroll
        for (int i = 0; i < 2; ++i) {
            const int w = tid + i * 256;     // 0..511 = 32 rows * 16 units
            const int r = w >> 4;
            const int u = w & 15;
            const uint32_t so = swz256(r, u);
            const size_t go = (size_t)(c * 32 + r) * 2048 + (size_t)u * 16;
            CP_ASYNC16(sb + 0 * KVT_B + so, gk + go);
            CP_ASYNC16(sb + 1 * KVT_B + so, gv + go);
        }
    };

    float acc[2][8][4];
    #pragma unroll
    for (int mt = 0; mt < 2; mt++)
        #pragma unroll
        for (int nt = 0; nt < 8; nt++)
            #pragma unroll
            for (int k = 0; k < 4; k++) acc[mt][nt][k] = 0.f;

    load_stage(0, 0); CP_COMMIT();
    load_stage(1, 1); CP_COMMIT();

    const int NC = 16;                   // 512 n / 32
    for (int c = 0; c < NC; ++c) {
        if (c + 2 < NC) {
            load_stage((c + 2) % 3, c + 2); CP_COMMIT();
            CP_WAIT(2);
        } else if (c + 1 < NC) {
            CP_WAIT(1);
        } else {
            CP_WAIT(0);
        }
        __syncthreads();

        const uint32_t sb = su + (c % 3) * KVSTG_B;
        #pragma unroll
        for (int kk = 0; kk < 2; ++kk) {       // 2 x 16 n per stage
            uint32_t ah[2][4];
            #pragma unroll
            for (int mt = 0; mt < 2; ++mt) {
                const int m0 = warp_m * 32 + mt * 16;          // d
                const int kr = kk * 16 + (lane & 7) + ((lane >> 4) & 1) * 8;   // n row
                const int mu = (m0 >> 3) + ((lane >> 3) & 1);  // 16B unit along d
                const uint32_t so = swz256(kr, mu);
                LDSM4T(ah[mt][0], ah[mt][1], ah[mt][2], ah[mt][3], sb + 0 * KVT_B + so);
            }
            #pragma unroll
            for (int p = 0; p < 4; ++p) {
                const int e0 = warp_n * 64 + p * 16;
                const int kr = kk * 16 + (lane & 7) + ((lane >> 3) & 1) * 8;
                const int eu = (e0 >> 3) + ((lane >> 4) & 1);
                const uint32_t so = swz256(kr, eu);
                uint32_t bh0, bh1, bh2, bh3;
                LDSM4T(bh0, bh1, bh2, bh3, sb + 1 * KVT_B + so);
                #pragma unroll
                for (int mt = 0; mt < 2; ++mt) {
                    MMAF16(acc[mt][2 * p],     ah[mt][0], ah[mt][1], ah[mt][2], ah[mt][3], bh0, bh1);
                    MMAF16(acc[mt][2 * p + 1], ah[mt][0], ah[mt][1], ah[mt][2], ah[mt][3], bh2, bh3);
                }
            }
        }
        __syncthreads();
    }

    float* outp = g_kv + (size_t)bh * HDq * HDq;
    #pragma unroll
    for (int mt = 0; mt < 2; ++mt) {
        const int d0 = warp_m * 32 + mt * 16 + (lane >> 2);
        const int d1 = d0 + 8;
        #pragma unroll
        for (int nt = 0; nt < 8; ++nt) {
            const int e = warp_n * 64 + nt * 8 + (lane & 3) * 2;
            atomicAdd(&outp[d0 * HDq + e],     acc[mt][nt][0]);
            atomicAdd(&outp[d0 * HDq + e + 1], acc[mt][nt][1]);
            atomicAdd(&outp[d1 * HDq + e],     acc[mt][nt][2]);
            atomicAdd(&outp[d1 * HDq + e + 1], acc[mt][nt][3]);
        }
    }
}

// ---------------------------------------------------------------------------
// Kernel 5: out[n][e] = sum_d q[n][d] kv[d][e].  HMMA 2-term (q@kvh + q@kvl).
// 256 rows per CTA: kv converted once, q tiles double-buffered.
// ---------------------------------------------------------------------------
#define OUT_QT_B  (128 * 256)          // 32KB per q tile
#define OUT_SMEM  (4 * OUT_QT_B)       // 128KB: q0, q1, kvh, kvl

__global__ __launch_bounds__(256, 1) void mma_out_gemm(float* __restrict__ out) {
    extern __shared__ char smem[];
    const uint32_t su = smem_u32(smem);
    const int tid = threadIdx.x;
    const int lane = tid & 31;
    const int wid = tid >> 5;
    const int warp_m = wid & 3;
    const int warp_n = wid >> 2;
    const int n0 = blockIdx.x * 256;
    const int bh = blockIdx.y;
    const int b = bh >> 3, h = bh & 7;

    const char* gq = (const char*)g_q + ((size_t)(b * Nq + n0) * Dq + h * HDq) * 2;

    auto load_q_tile = [&](int t) {      // t = 0/1 -> rows [t*128, t*128+128)
        const uint32_t sb = su + t * OUT_QT_B;
        const char* src = gq + (size_t)t * 128 * 2048;
        #pragma unroll
        for (int i = 0; i < 8; ++i) {
            const int w = tid + i * 256;     // 0..2047 = 128 rows * 16 units
            const int r = w >> 4;
            const int u = w & 15;
            CP_ASYNC16(sb + swz256(r, u), src + (size_t)r * 2048 + (size_t)u * 16);
        }
    };

    load_q_tile(0); CP_COMMIT();

    // convert kv f32 -> fp16 hi/lo into swizzled smem (once per CTA)
    {
        const float* kvp = g_kv + (size_t)bh * HDq * HDq;
        __half* s_kvh = (__half*)(smem + 2 * OUT_QT_B);
        __half* s_kvl = (__half*)(smem + 3 * OUT_QT_B);
        #pragma unroll
        for (int i = 0; i < 64; ++i) {
            const int idx = tid + i * 256;   // 0..16383
            const int d = idx >> 7, e = idx & 127;
            const float v = kvp[idx];
            __half hh, hl;
            hsplit(v, hh, hl);
            const uint32_t off = swz256(d, e >> 3) + (e & 7) * 2;
            *reinterpret_cast<__half*>((char*)s_kvh + off) = hh;
            *reinterpret_cast<__half*>((char*)s_kvl + off) = hl;
        }
    }
    load_q_tile(1); CP_COMMIT();

    auto compute_tile = [&](int t) {
        const uint32_t qb = su + t * OUT_QT_B;
        float acc[2][8][4];
        #pragma unroll
        for (int mt = 0; mt < 2; mt++)
            #pragma unroll
            for (int nt = 0; nt < 8; nt++)
                #pragma unroll
                for (int k = 0; k < 4; k++) acc[mt][nt][k] = 0.f;

        #pragma unroll
        for (int kk = 0; kk < 8; ++kk) {         // K = d = 128
            uint32_t ah[2][4];
            #pragma unroll
            for (int mt = 0; mt < 2; ++mt) {
                const int r = warp_m * 32 + mt * 16 + (lane & 15);
                const int u = kk * 2 + (lane >> 4);
                LDSM4(ah[mt][0], ah[mt][1], ah[mt][2], ah[mt][3], qb + swz256(r, u));
            }
            #pragma unroll
            for (int p = 0; p < 4; ++p) {
                const int e0 = warp_n * 64 + p * 16;
                const int kr = kk * 16 + (lane & 7) + ((lane >> 3) & 1) * 8;   // d row
                const int eu = (e0 >> 3) + ((lane >> 4) & 1);
                const uint32_t so = swz256(kr, eu);
                uint32_t bh0, bh1, bh2, bh3, bl0, bl1, bl2, bl3;
                LDSM4T(bh0, bh1, bh2, bh3, su + 2 * OUT_QT_B + so);
                LDSM4T(bl0, bl1, bl2, bl3, su + 3 * OUT_QT_B + so);
                #pragma unroll
                for (int mt = 0; mt < 2; ++mt) {
                    MMAF16(acc[mt][2 * p],     ah[mt][0], ah[mt][1], ah[mt][2], ah[mt][3], bh0, bh1);
                    MMAF16(acc[mt][2 * p + 1], ah[mt][0], ah[mt][1], ah[mt][2], ah[mt][3], bh2, bh3);
                    MMAF16(acc[mt][2 * p],     ah[mt][0], ah[mt][1], ah[mt][2], ah[mt][3], bl0, bl1);
                    MMAF16(acc[mt][2 * p + 1], ah[mt][0], ah[mt][1], ah[mt][2], ah[mt][3], bl2, bl3);
                }
            }
        }

        #pragma unroll
        for (int mt = 0; mt < 2; ++mt) {
            const int r0 = n0 + t * 128 + warp_m * 32 + mt * 16 + (lane >> 2);
            const int r1 = r0 + 8;
            #pragma unroll
            for (int nt = 0; nt < 8; ++nt) {
                const int e = warp_n * 64 + nt * 8 + (lane & 3) * 2;
                float* o0 = out + (size_t)(b * Nq + r0) * Dq + h * HDq + e;
                float* o1 = out + (size_t)(b * Nq + r1) * Dq + h * HDq + e;
                *reinterpret_cast<float2*>(o0) = make_float2(acc[mt][nt][0], acc[mt][nt][1]);
                *reinterpret_cast<float2*>(o1) = make_float2(acc[mt][nt][2], acc[mt][nt][3]);
            }
        }
    };

    CP_WAIT(1);          // q tile 0 landed
    __syncthreads();     // also orders the kv smem conversion
    compute_tile(0);
    CP_WAIT(0);          // q tile 1 landed
    __syncthreads();
    compute_tile(1);
}

// ---------------------------------------------------------------------------
// Launch: inputs in metadata order: x, mask, w_qkv, gamma, beta.
// ---------------------------------------------------------------------------
extern "C" void kernel_launch(void* const* d_in, const int* in_sizes, int n_in,
                              void* d_out, int out_size) {
    const float* x     = (const float*)d_in[0];
    const void*  mask  = d_in[1];
    const float* w     = (const float*)d_in[2];
    const float* gamma = (const float*)d_in[3];
    const float* beta  = (const float*)d_in[4];
    float* out         = (float*)d_out;

    static int smem_set = 0;
    if (!smem_set) {
        cudaFuncSetAttribute(mma_qkv_gemm, cudaFuncAttributeMaxDynamicSharedMemorySize, QKV_SMEM);
        cudaFuncSetAttribute(mma_kv_gemm,  cudaFuncAttributeMaxDynamicSharedMemorySize, KV_SMEM);
        cudaFuncSetAttribute(mma_out_gemm, cudaFuncAttributeMaxDynamicSharedMemorySize, OUT_SMEM);
        smem_set = 1;
    }

    mask_detect<<<1, 256>>>((const int*)mask);
    mask_expand<<<(Bq * Nq + 255) / 256, 256>>>(mask);
    ln_split<<<Bq * Nq, 256>>>(x, gamma, beta);
    w_split<<<dim3(TDq / 32, Dq / 32), dim3(32, 8)>>>(w);
    mma_qkv_gemm<<<dim3(TDq / 256, (Bq * Nq) / 128), 256, QKV_SMEM>>>();
    zero_kv<<<(Bq * Hq * HDq * HDq + 255) / 256, 256>>>();
    mma_kv_gemm<<<dim3(Bq * Hq, KV_SPLIT), 256, KV_SMEM>>>();
    mma_out_gemm<<<dim3(Nq / 256, Bq * Hq), 256, OUT_SMEM>>>(out);
}